// round 9
// baseline (speedup 1.0000x reference)
#include <cuda_runtime.h>
#include <cuda_bf16.h>
#include <math.h>

#define Mm 64
#define Nn 16
#define Dd 300
#define Ff 768
#define VOCAB 100000
#define SURF_L 4
#define CTX_L 50
#define DOC_L 100
#define BODY_L 200
#define HD 60
#define NH 5

#define KDP 152              // u32 pairs per tap row in g_Wb (304 padded d)
#define XSTR 168             // X row stride in u32 pairs (336 elems, bank-staggered)
#define WSTR 84              // W slab row stride in u32 pairs (168 elems)

typedef unsigned long long u64;
typedef unsigned int u32;

// ---------------- scratch (__device__ globals, no allocation) ----------------
__device__ float g_Wt_ms[2 * Dd * Ff];
__device__ u32 g_WbH[Ff * 5 * KDP];
__device__ u32 g_WbL[Ff * 5 * KDP];
__device__ float g_ms[Mm * Ff];
__device__ float g_mc[Mm * Ff];
__device__ float g_comb_part[Nn * 6 * 304];   // [n][chunk z][h*60+j]
__device__ float g_attscore[Nn];
__device__ float g_local[Mm * Nn];
__device__ float g_tn[Nn];
__device__ float g_cosdt[Nn];

__device__ __forceinline__ int safe_id(const int* p, int i) {
    int v = p[i];
    return v < 0 ? 0 : (v >= VOCAB ? VOCAB - 1 : v);
}
__device__ __forceinline__ u32 smem_to_u32(const void* p) {
    u32 a;
    asm("{ .reg .u64 t; cvta.to.shared.u64 t, %1; cvt.u32.u64 %0, t; }" : "=r"(a) : "l"(p));
    return a;
}
__device__ __forceinline__ void ldsm_x4(u32 addr, u32& r0, u32& r1, u32& r2, u32& r3) {
    asm volatile("ldmatrix.sync.aligned.m8n8.x4.shared.b16 {%0,%1,%2,%3}, [%4];"
                 : "=r"(r0), "=r"(r1), "=r"(r2), "=r"(r3) : "r"(addr));
}
__device__ __forceinline__ void mma_bf16(float* c, u32 a0, u32 a1, u32 a2, u32 a3,
                                         u32 b0, u32 b1) {
    asm volatile(
        "mma.sync.aligned.m16n8k16.row.col.f32.bf16.bf16.f32 "
        "{%0,%1,%2,%3}, {%4,%5,%6,%7}, {%8,%9}, {%0,%1,%2,%3};"
        : "+f"(c[0]), "+f"(c[1]), "+f"(c[2]), "+f"(c[3])
        : "r"(a0), "r"(a1), "r"(a2), "r"(a3), "r"(b0), "r"(b1));
}
__device__ __forceinline__ void split_pair(float a, float b, u32& hi, u32& lo) {
    __nv_bfloat16 ha = __float2bfloat16(a);
    __nv_bfloat16 hb = __float2bfloat16(b);
    __nv_bfloat16 la = __float2bfloat16(a - __bfloat162float(ha));
    __nv_bfloat16 lb = __float2bfloat16(b - __bfloat162float(hb));
    hi = ((u32)__bfloat16_as_ushort(hb) << 16) | (u32)__bfloat16_as_ushort(ha);
    lo = ((u32)__bfloat16_as_ushort(lb) << 16) | (u32)__bfloat16_as_ushort(la);
}

__device__ __forceinline__ float warp_sum(float v) {
#pragma unroll
    for (int o = 16; o; o >>= 1) v += __shfl_xor_sync(0xFFFFFFFFu, v, o);
    return v;
}
__device__ __forceinline__ float warp_max(float v) {
#pragma unroll
    for (int o = 16; o; o >>= 1) v = fmaxf(v, __shfl_xor_sync(0xFFFFFFFFu, v, o));
    return v;
}
__device__ __forceinline__ float r16_sum(float v) {
#pragma unroll
    for (int o = 8; o; o >>= 1) v += __shfl_xor_sync(0xFFFFu, v, o, 16);
    return v;
}
__device__ __forceinline__ float r16_max(float v) {
#pragma unroll
    for (int o = 8; o; o >>= 1) v = fmaxf(v, __shfl_xor_sync(0xFFFFu, v, o, 16));
    return v;
}
__device__ __forceinline__ float r16_min(float v) {
#pragma unroll
    for (int o = 8; o; o >>= 1) v = fminf(v, __shfl_xor_sync(0xFFFFu, v, o, 16));
    return v;
}

// ---------------- weight prep ----------------
__global__ void wprep_kernel(const float* __restrict__ Wms,
                             const float* __restrict__ Wmc) {
    int idx = blockIdx.x * blockDim.x + threadIdx.x;
    const int nW = Ff * 5 * KDP;
    if (idx < nW) {
        int f = idx / (5 * KDP);
        int r = idx - f * (5 * KDP);
        int tap = r / KDP;
        int dp = r - tap * KDP;
        int d = 2 * dp;
        float a = (d < Dd) ? Wmc[(size_t)f * Dd * 5 + d * 5 + tap] : 0.f;
        float b = (d + 1 < Dd) ? Wmc[(size_t)f * Dd * 5 + (d + 1) * 5 + tap] : 0.f;
        u32 hi, lo;
        split_pair(a, b, hi, lo);
        g_WbH[idx] = hi;
        g_WbL[idx] = lo;
    } else {
        int i = idx - nW;
        if (i < 2 * Dd * Ff) {
            int f = i % Ff;
            int rest = i / Ff;
            int d = rest % Dd;
            int k = rest / Dd;
            g_Wt_ms[i] = Wms[(size_t)f * Dd * 2 + d * 2 + k];
        }
    }
}

// ---------------- surface conv ----------------
__launch_bounds__(192)
__global__ void conv_ms_kernel(const int* __restrict__ ids,
                               const float* __restrict__ emb,
                               const float* __restrict__ bias) {
    const int m = blockIdx.x;
    const int tid = threadIdx.x;
    __shared__ float Xs[SURF_L * Dd];
    for (int i = tid; i < SURF_L * Dd; i += 192) {
        int l = i / Dd, d = i - l * Dd;
        Xs[i] = emb[(size_t)safe_id(ids, m * SURF_L + l) * Dd + d];
    }
    __syncthreads();
    float4 acc[3];
#pragma unroll
    for (int t = 0; t < 3; t++) acc[t] = make_float4(0.f, 0.f, 0.f, 0.f);
#pragma unroll
    for (int k = 0; k < 2; k++) {
        const float4* __restrict__ wp = (const float4*)(g_Wt_ms + (size_t)k * Dd * Ff) + tid;
        const float* __restrict__ xk = Xs + k * Dd;
        for (int d = 0; d < Dd; d++) {
            float4 w = wp[(size_t)d * (Ff / 4)];
#pragma unroll
            for (int t = 0; t < 3; t++) {
                float xv = xk[t * Dd + d];
                acc[t].x = fmaf(xv, w.x, acc[t].x);
                acc[t].y = fmaf(xv, w.y, acc[t].y);
                acc[t].z = fmaf(xv, w.z, acc[t].z);
                acc[t].w = fmaf(xv, w.w, acc[t].w);
            }
        }
    }
    float4 b4 = ((const float4*)bias)[tid];
    float4 s = make_float4(0.f, 0.f, 0.f, 0.f);
#pragma unroll
    for (int t = 0; t < 3; t++) {
        s.x += fmaxf(acc[t].x + b4.x, 0.f);
        s.y += fmaxf(acc[t].y + b4.y, 0.f);
        s.z += fmaxf(acc[t].z + b4.z, 0.f);
        s.w += fmaxf(acc[t].w + b4.w, 0.f);
    }
    s.x *= (1.f / 3.f); s.y *= (1.f / 3.f); s.z *= (1.f / 3.f); s.w *= (1.f / 3.f);
    ((float4*)(g_ms + (size_t)m * Ff))[tid] = s;
}

// ---------------- context conv: mma.sync, 1 mention/block, k-halved W staging ----------------
// X: [52 rows][XSTR pairs] hi then lo. W slab: [128 f][WSTR pairs] per (tap, half, kh).
#define XH_OFF 0
#define XHALF_B (52 * XSTR * 4)               // 34944
#define XL_OFF XHALF_B
#define WS_OFF (2 * XHALF_B)                  // 69888
#define SMEM_CONV (WS_OFF + 128 * WSTR * 4)   // +43008 = 112896

__global__ void __launch_bounds__(128, 2)
conv_mma2_kernel(const int* __restrict__ ids,
                 const float* __restrict__ emb,
                 const float* __restrict__ bias) {
    extern __shared__ char smem[];
    const int tid = threadIdx.x;
    const int lane = tid & 31;
    const int w = tid >> 5;          // 4 warps: 32 f each
    const int m = blockIdx.x;
    const int f0 = blockIdx.y * 128;

    // gather + split X (rows 0..49 data, 50..51 zero; pairs >=152 zero)
    u32* xh = (u32*)(smem + XH_OFF);
    u32* xl = (u32*)(smem + XL_OFF);
    for (int i = tid; i < 52 * XSTR; i += 128) {
        int row = i / XSTR;
        int dp = i - row * XSTR;
        float a = 0.f, b = 0.f;
        if (row < CTX_L && dp < KDP) {
            int d = 2 * dp;
            const float* er = emb + (size_t)safe_id(ids, m * CTX_L + row) * Dd;
            if (d < Dd) a = er[d];
            if (d + 1 < Dd) b = er[d + 1];
        }
        u32 hi, lo;
        split_pair(a, b, hi, lo);
        xh[i] = hi;
        xl[i] = lo;
    }

    const u32 sb = smem_to_u32(smem);
    const u32 wsb = sb + WS_OFF;

    const int a_r = lane & 15;
    const int a_k = (lane >> 4) << 3;
    const int b_n = ((lane >> 4) << 3) + (lane & 7);
    const int b_k = ((lane >> 3) & 1) << 3;

    float C[3][4][4];
#pragma unroll
    for (int mt = 0; mt < 3; mt++)
#pragma unroll
        for (int nt = 0; nt < 4; nt++)
#pragma unroll
            for (int j = 0; j < 4; j++) C[mt][nt][j] = 0.f;

    for (int half = 0; half < 2; half++) {
        const u32* __restrict__ wsrc = half ? g_WbL : g_WbH;
        for (int tap = 0; tap < 5; tap++) {
            for (int kh = 0; kh < 2; kh++) {
                const int npair = kh ? 72 : 80;     // pairs this k-half
                const int nvec = npair >> 2;        // uint4 count per f
                __syncthreads();
                {   // stage W slab [128][npair pairs], row stride WSTR pairs
                    const uint4* __restrict__ src = (const uint4*)wsrc;
                    uint4* __restrict__ dst = (uint4*)(smem + WS_OFF);
                    for (int i = tid; i < 128 * nvec; i += 128) {
                        int fi = i / nvec, c = i - fi * nvec;
                        dst[fi * (WSTR >> 2) + c] =
                            src[(((size_t)(f0 + fi) * 5 + tap) * KDP + kh * 80) / 4 + c];
                    }
                }
                __syncthreads();
                const int nks = kh ? 9 : 10;
                const int xk0 = kh * 160;
                for (int ks = 0; ks < nks; ks++) {
                    const int k0 = ks * 16;
                    u32 Bf[4][2];
#pragma unroll
                    for (int p = 0; p < 2; p++) {
                        u32 addr = wsb +
                            (u32)(((w * 32 + p * 16 + b_n) * (WSTR * 2) + k0 + b_k) * 2);
                        ldsm_x4(addr, Bf[2 * p][0], Bf[2 * p][1],
                                Bf[2 * p + 1][0], Bf[2 * p + 1][1]);
                    }
#pragma unroll
                    for (int mt = 0; mt < 3; mt++) {
                        u32 aoff =
                            (u32)(((mt * 16 + tap + a_r) * (XSTR * 2) + xk0 + k0 + a_k) * 2);
                        u32 A0, A1, A2, A3;
                        ldsm_x4(sb + XH_OFF + aoff, A0, A1, A2, A3);
#pragma unroll
                        for (int nt = 0; nt < 4; nt++)
                            mma_bf16(C[mt][nt], A0, A1, A2, A3, Bf[nt][0], Bf[nt][1]);
                        if (half == 0) {
                            ldsm_x4(sb + XL_OFF + aoff, A0, A1, A2, A3);
#pragma unroll
                            for (int nt = 0; nt < 4; nt++)
                                mma_bf16(C[mt][nt], A0, A1, A2, A3, Bf[nt][0], Bf[nt][1]);
                        }
                    }
                }
            }
        }
    }

    // epilogue: stage C [48 t][128 f], bias+relu+sum over t
    __syncthreads();
    float* stg = (float*)(smem + WS_OFF);
#pragma unroll
    for (int mt = 0; mt < 3; mt++)
#pragma unroll
        for (int nt = 0; nt < 4; nt++) {
            int row = mt * 16 + (lane >> 2);
            int col = w * 32 + nt * 8 + (lane & 3) * 2;
            stg[row * 128 + col] = C[mt][nt][0];
            stg[row * 128 + col + 1] = C[mt][nt][1];
            stg[(row + 8) * 128 + col] = C[mt][nt][2];
            stg[(row + 8) * 128 + col + 1] = C[mt][nt][3];
        }
    __syncthreads();
    {
        float b = bias[f0 + tid];
        float s = 0.f;
        for (int t = 0; t < 46; t++) s += fmaxf(stg[t * 128 + tid] + b, 0.f);
        g_mc[(size_t)m * Ff + f0 + tid] = s * (1.0f / 46.0f);
    }
}

// ---------------- cross attention: q chunked into 50-row blocks ----------------
// grid (Nn, NH, 6): z<2 -> dir0 (q=doc, k=body) chunk z; z>=2 -> dir1 (q=body, k=doc) chunk z-2.
__global__ void __launch_bounds__(256, 2)
attn_kernel(const int* __restrict__ doc_ids,
            const int* __restrict__ body_ids,
            const float* __restrict__ emb) {
    const int n = blockIdx.x, h = blockIdx.y, z = blockIdx.z;
    const int dir = (z < 2) ? 0 : 1;
    const int q0 = (dir == 0 ? z : z - 2) * 50;
    const int Lk = dir == 0 ? BODY_L : DOC_L;
    extern __shared__ float sh[];
    float* qs = sh;                 // 50*60
    float* ks = qs + 50 * HD;       // Lk*60
    float* S = ks + Lk * HD;        // 50*Lk
    __shared__ float red[8][64];

    const int tid = threadIdx.x;    // 256
    const int* qsrc = (dir == 0) ? (doc_ids + q0) : (body_ids + n * BODY_L + q0);
    const int* ksrc = (dir == 0) ? (body_ids + n * BODY_L) : doc_ids;

    for (int i = tid; i < 50 * HD; i += 256) {
        int l = i / HD, j = i - l * HD;
        qs[i] = emb[(size_t)safe_id(qsrc, l) * Dd + h * HD + j];
    }
    for (int i = tid; i < Lk * HD; i += 256) {
        int l = i / HD, j = i - l * HD;
        ks[i] = emb[(size_t)safe_id(ksrc, l) * Dd + h * HD + j];
    }
    __syncthreads();

    const float scale = rsqrtf((float)HD);
    const float4* qs4 = (const float4*)qs;
    const float4* ks4 = (const float4*)ks;
    for (int idx = tid; idx < 50 * Lk; idx += 256) {
        int q = idx / Lk, k = idx - q * Lk;
        float4 a = make_float4(0.f, 0.f, 0.f, 0.f);
#pragma unroll
        for (int j = 0; j < 15; j++) {
            float4 qv = qs4[q * 15 + j];
            float4 kv = ks4[k * 15 + j];
            a.x = fmaf(qv.x, kv.x, a.x);
            a.y = fmaf(qv.y, kv.y, a.y);
            a.z = fmaf(qv.z, kv.z, a.z);
            a.w = fmaf(qv.w, kv.w, a.w);
        }
        S[idx] = (a.x + a.y + a.z + a.w) * scale;
    }
    __syncthreads();

    const int wid = tid >> 5, lane = tid & 31;
    for (int q = wid; q < 50; q += 8) {
        float* row = S + q * Lk;
        float mx = -1e30f;
        for (int k = lane; k < Lk; k += 32) mx = fmaxf(mx, row[k]);
        mx = warp_max(mx);
        float sum = 0.f;
        for (int k = lane; k < Lk; k += 32) {
            float e = expf(row[k] - mx);
            row[k] = e;
            sum += e;
        }
        sum = warp_sum(sum);
        float inv = 1.f / sum;
        for (int k = lane; k < Lk; k += 32) row[k] *= inv;
    }
    __syncthreads();

    // PV: warp per row, lanes 0..29 own float2 dims; max over rows
    if (lane < 30) {
        const float2* ks2 = (const float2*)ks;
        float2 mx = make_float2(-1e30f, -1e30f);
        for (int q = wid; q < 50; q += 8) {
            const float* row = S + q * Lk;
            float2 o0 = make_float2(0.f, 0.f), o1 = make_float2(0.f, 0.f);
            for (int k = 0; k < Lk; k += 2) {
                float p0 = row[k], p1 = row[k + 1];
                float2 v0 = ks2[k * 30 + lane];
                float2 v1 = ks2[(k + 1) * 30 + lane];
                o0.x = fmaf(p0, v0.x, o0.x);
                o0.y = fmaf(p0, v0.y, o0.y);
                o1.x = fmaf(p1, v1.x, o1.x);
                o1.y = fmaf(p1, v1.y, o1.y);
            }
            mx.x = fmaxf(mx.x, o0.x + o1.x);
            mx.y = fmaxf(mx.y, o0.y + o1.y);
        }
        red[wid][2 * lane] = mx.x;
        red[wid][2 * lane + 1] = mx.y;
    }
    __syncthreads();
    if (tid < 60) {
        float mxv = -1e30f;
#pragma unroll
        for (int g = 0; g < 8; g++) mxv = fmaxf(mxv, red[g][tid]);
        g_comb_part[(n * 6 + z) * 304 + h * HD + tid] = mxv;
    }
}

// ---------------- attention MLP (combines chunk maxes) ----------------
__global__ void attmlp_kernel(const float* __restrict__ W1,
                              const float* __restrict__ b1,
                              const float* __restrict__ W2,
                              const float* __restrict__ b2) {
    const int n = blockIdx.x;
    __shared__ float cb[600];
    __shared__ float partial[10];
    const int tid = threadIdx.x;  // 320
    const float* part = g_comb_part + n * 6 * 304;
    for (int i = tid; i < 600; i += 320) {
        float v;
        if (i < 300) {
            v = fmaxf(part[0 * 304 + i], part[1 * 304 + i]);
        } else {
            int j = i - 300;
            v = fmaxf(fmaxf(part[2 * 304 + j], part[3 * 304 + j]),
                      fmaxf(part[4 * 304 + j], part[5 * 304 + j]));
        }
        cb[i] = v;
    }
    __syncthreads();
    float v = 0.f;
    if (tid < 300) {
        float a0 = b1[tid], a1 = 0.f, a2 = 0.f, a3 = 0.f;
        for (int i = 0; i < 600; i += 4) {
            a0 = fmaf(cb[i], W1[i * 300 + tid], a0);
            a1 = fmaf(cb[i + 1], W1[(i + 1) * 300 + tid], a1);
            a2 = fmaf(cb[i + 2], W1[(i + 2) * 300 + tid], a2);
            a3 = fmaf(cb[i + 3], W1[(i + 3) * 300 + tid], a3);
        }
        float a = (a0 + a1) + (a2 + a3);
        a = fmaxf(a, 0.f);
        v = a * W2[tid];
    }
    v = warp_sum(v);
    if ((tid & 31) == 0) partial[tid >> 5] = v;
    __syncthreads();
    if (tid == 0) {
        float s = 0.f;
        for (int w = 0; w < 10; w++) s += partial[w];
        s += b2[0];
        g_attscore[n] = 1.f / (1.f + expf(-s));
    }
}

// ---------------- LocalCtxAttRanker ----------------
__global__ void localctx_kernel(const int* __restrict__ cand_ids,
                                const int* __restrict__ ctx_ids,
                                const float* __restrict__ emb) {
    const int m = blockIdx.x;
    extern __shared__ float sh[];
    float* cs = sh;
    float* xs = cs + Nn * Dd;
    float* tok = xs + CTX_L * Dd;
    float* p = tok + Nn * CTX_L;
    float* ctxv = p + CTX_L;
    const int tid = threadIdx.x;  // 256

    for (int i = tid; i < Nn * Dd; i += 256) {
        int n = i / Dd, d = i - n * Dd;
        cs[i] = emb[(size_t)safe_id(cand_ids, m * Nn + n) * Dd + d];
    }
    for (int i = tid; i < CTX_L * Dd; i += 256) {
        int t = i / Dd, d = i - t * Dd;
        xs[i] = emb[(size_t)safe_id(ctx_ids, m * CTX_L + t) * Dd + d];
    }
    __syncthreads();

    const float4* cs4 = (const float4*)cs;
    const float4* xs4 = (const float4*)xs;
    for (int idx = tid; idx < Nn * CTX_L; idx += 256) {
        int n = idx / CTX_L, t = idx - n * CTX_L;
        float4 a = make_float4(0.f, 0.f, 0.f, 0.f);
#pragma unroll 5
        for (int j = 0; j < 75; j++) {
            float4 cv = cs4[n * 75 + j];
            float4 xv = xs4[t * 75 + j];
            a.x = fmaf(cv.x, xv.x, a.x);
            a.y = fmaf(cv.y, xv.y, a.y);
            a.z = fmaf(cv.z, xv.z, a.z);
            a.w = fmaf(cv.w, xv.w, a.w);
        }
        tok[idx] = (a.x + a.y) + (a.z + a.w);
    }
    __syncthreads();
    if (tid < CTX_L) {
        float mx = -1e30f;
        for (int n = 0; n < Nn; n++) mx = fmaxf(mx, tok[n * CTX_L + tid]);
        p[tid] = mx;
    }
    __syncthreads();
    if (tid < 32) {
        float mx = -1e30f;
        for (int t = tid; t < CTX_L; t += 32) mx = fmaxf(mx, p[t]);
        mx = warp_max(mx);
        float sum = 0.f;
        for (int t = tid; t < CTX_L; t += 32) {
            float e = expf(p[t] - mx);
            p[t] = e;
            sum += e;
        }
        sum = warp_sum(sum);
        float inv = 1.f / sum;
        for (int t = tid; t < CTX_L; t += 32) p[t] *= inv;
    }
    __syncthreads();
    for (int d = tid; d < Dd; d += 256) {
        float s = 0.f;
        for (int t = 0; t < CTX_L; t++) s = fmaf(p[t], xs[t * Dd + d], s);
        ctxv[d] = s;
    }
    __syncthreads();
    const int wid = tid >> 5, lane = tid & 31;
    for (int n = wid; n < Nn; n += 8) {
        float s = 0.f;
        for (int d = lane; d < Dd; d += 32) s = fmaf(cs[n * Dd + d], ctxv[d], s);
        s = warp_sum(s);
        if (lane == 0) g_local[m * Nn + n] = s;
    }
}

// ---------------- prep ----------------
__global__ void prep_kernel(const float* __restrict__ title,
                            const float* __restrict__ md) {
    const int w = threadIdx.x >> 5, lane = threadIdx.x & 31;
    float st2 = 0.f, smt = 0.f, sm2 = 0.f;
    for (int j = lane; j < Ff; j += 32) {
        float t = title[w * Ff + j];
        float mv = md[j];
        st2 = fmaf(t, t, st2);
        smt = fmaf(t, mv, smt);
        sm2 = fmaf(mv, mv, sm2);
    }
    st2 = warp_sum(st2);
    smt = warp_sum(smt);
    sm2 = warp_sum(sm2);
    if (lane == 0) {
        float tnv = sqrtf(st2);
        g_tn[w] = tnv;
        g_cosdt[w] = smt / (fmaxf(sqrtf(sm2), 1e-6f) * fmaxf(tnv, 1e-6f));
    }
}

// ---------------- final ----------------
__global__ void final_kernel(const float* __restrict__ title,
                             const float* __restrict__ prior,
                             const float* __restrict__ hand,
                             const float* __restrict__ w7,
                             const float* __restrict__ b7,
                             float* __restrict__ out) {
    const int m = blockIdx.x;
    const int tid = threadIdx.x;  // 256
    const int wid = tid >> 5, lane = tid & 31;
    __shared__ float nms_s, nmc_s;
    __shared__ float dst[Nn], dct[Nn], sc[Nn];

    if (wid == 0) {
        float s = 0.f;
        for (int j = lane; j < Ff; j += 32) {
            float v = g_ms[m * Ff + j];
            s = fmaf(v, v, s);
        }
        s = warp_sum(s);
        if (lane == 0) nms_s = fmaxf(sqrtf(s), 1e-6f);
    }
    if (wid == 1) {
        float s = 0.f;
        for (int j = lane; j < Ff; j += 32) {
            float v = g_mc[m * Ff + j];
            s = fmaf(v, v, s);
        }
        s = warp_sum(s);
        if (lane == 0) nmc_s = fmaxf(sqrtf(s), 1e-6f);
    }
    for (int item = wid; item < 32; item += 8) {
        int n = item & 15;
        int which = item >> 4;
        const float* a = which ? (g_mc + m * Ff) : (g_ms + m * Ff);
        float s = 0.f;
        for (int j = lane; j < Ff; j += 32) s = fmaf(a[j], title[n * Ff + j], s);
        s = warp_sum(s);
        if (lane == 0) {
            if (which) dct[n] = s;
            else dst[n] = s;
        }
    }
    __syncthreads();

    if (tid < Nn) {
        int n = tid;
        float tc = fmaxf(g_tn[n], 1e-6f);
        float cst = dst[n] / (nms_s * tc);
        float cct = dct[n] / (nmc_s * tc);
        float s = b7[0];
        s = fmaf(w7[0], hand[n], s);
        s = fmaf(w7[1], prior[n], s);
        s = fmaf(w7[2], g_local[m * Nn + n], s);
        s = fmaf(w7[3], g_attscore[n], s);
        s = fmaf(w7[4], cst, s);
        s = fmaf(w7[5], g_cosdt[n], s);
        s = fmaf(w7[6], cct, s);
        sc[n] = s;
    }
    __syncthreads();
    if (tid < Nn) {
        float x = sc[tid];
        float mu = r16_sum(x) * (1.f / 16.f);
        float dv = x - mu;
        float var = r16_sum(dv * dv) * (1.f / 15.f);
        float z = dv / sqrtf(var);
        out[m * Nn + tid] = z;
        float zmax = r16_max(z);
        float zmin = r16_min(z);
        float e = expf(z - zmax);
        float es = r16_sum(e);
        out[Mm * Nn + m * Nn + tid] = e / es;
        float u = (z + 1.f - zmin) / (zmax - zmin);
        float us = r16_sum(u);
        out[2 * Mm * Nn + m * Nn + tid] = u / us;
    }
}

// ---------------- launch ----------------
extern "C" void kernel_launch(void* const* d_in, const int* in_sizes, int n_in,
                              void* d_out, int out_size) {
    int e = -1;
    for (int i = 0; i < n_in; i++) {
        if (in_sizes[i] == VOCAB * Dd) { e = i; break; }
    }
    if (e < 0) e = 14;

    const int* mention_vec  = (const int*)d_in[e - 11];
    const int* context_vec  = (const int*)d_in[e - 10];
    const int* doc_vec      = (const int*)d_in[e - 9];
    const float* title      = (const float*)d_in[e - 8];
    const int* body_vec     = (const int*)d_in[e - 7];
    const float* prior      = (const float*)d_in[e - 5];
    const int* men2cands    = (const int*)d_in[e - 4];
    const int* contexts_ids = (const int*)d_in[e - 3];
    const float* hand       = (const float*)d_in[e - 2];
    const float* bert       = (const float*)d_in[e - 1];
    const float* emb        = (const float*)d_in[e];
    const float* Wms        = (const float*)d_in[e + 1];
    const float* bms        = (const float*)d_in[e + 2];
    const float* Wmc        = (const float*)d_in[e + 3];
    const float* bmc        = (const float*)d_in[e + 4];
    const float* w7         = (const float*)d_in[e + 5];
    const float* b7         = (const float*)d_in[e + 6];
    const float* W1         = (const float*)d_in[e + 7];
    const float* b1         = (const float*)d_in[e + 8];
    const float* W2         = (const float*)d_in[e + 9];
    const float* b2         = (const float*)d_in[e + 10];
    float* out = (float*)d_out;

    static bool s_init = false;
    static cudaStream_t s0, s1, s2;
    static cudaEvent_t evF, ev0, ev1, ev2;
    if (!s_init) {
        cudaStreamCreateWithFlags(&s0, cudaStreamNonBlocking);
        cudaStreamCreateWithFlags(&s1, cudaStreamNonBlocking);
        cudaStreamCreateWithFlags(&s2, cudaStreamNonBlocking);
        cudaEventCreateWithFlags(&evF, cudaEventDisableTiming);
        cudaEventCreateWithFlags(&ev0, cudaEventDisableTiming);
        cudaEventCreateWithFlags(&ev1, cudaEventDisableTiming);
        cudaEventCreateWithFlags(&ev2, cudaEventDisableTiming);
        s_init = true;
    }

    cudaFuncSetAttribute(attn_kernel, cudaFuncAttributeMaxDynamicSharedMemorySize, 100000);
    cudaFuncSetAttribute(localctx_kernel, cudaFuncAttributeMaxDynamicSharedMemorySize, 84000);
    cudaFuncSetAttribute(conv_mma2_kernel, cudaFuncAttributeMaxDynamicSharedMemorySize, SMEM_CONV);

    cudaEventRecord(evF, 0);
    cudaStreamWaitEvent(s0, evF, 0);
    cudaStreamWaitEvent(s1, evF, 0);
    cudaStreamWaitEvent(s2, evF, 0);

    // s0: weight prep -> convs
    wprep_kernel<<<(Ff * 5 * KDP + 2 * Dd * Ff + 255) / 256, 256, 0, s0>>>(Wms, Wmc);
    conv_ms_kernel<<<Mm, 192, 0, s0>>>(mention_vec, emb, bms);
    conv_mma2_kernel<<<dim3(Mm, Ff / 128), 128, SMEM_CONV, s0>>>(context_vec, emb, bmc);
    cudaEventRecord(ev0, s0);

    // s1: cross attention (chunked) + MLP score
    attn_kernel<<<dim3(Nn, NH, 6), 256, 100000, s1>>>(doc_vec, body_vec, emb);
    attmlp_kernel<<<Nn, 320, 0, s1>>>(W1, b1, W2, b2);
    cudaEventRecord(ev1, s1);

    // s2: local context ranker + title prep
    localctx_kernel<<<Mm, 256, 84000, s2>>>(men2cands, contexts_ids, emb);
    prep_kernel<<<1, 512, 0, s2>>>(title, bert);
    cudaEventRecord(ev2, s2);

    cudaStreamWaitEvent(0, ev0, 0);
    cudaStreamWaitEvent(0, ev1, 0);
    cudaStreamWaitEvent(0, ev2, 0);

    final_kernel<<<Mm, 256>>>(title, prior, hand, w7, b7, out);
}

// round 10
// speedup vs baseline: 1.4368x; 1.4368x over previous
#include <cuda_runtime.h>
#include <cuda_bf16.h>
#include <math.h>

#define Mm 64
#define Nn 16
#define Dd 300
#define Ff 768
#define VOCAB 100000
#define SURF_L 4
#define CTX_L 50
#define DOC_L 100
#define BODY_L 200
#define HD 60
#define NH 5

#define KD 304               // padded d per tap
#define KDP (KD / 2)         // u32 pairs per tap row = 152

typedef unsigned long long u64;
typedef unsigned int u32;

// ---------------- scratch (__device__ globals, no allocation) ----------------
__device__ float g_Wt_ms[2 * Dd * Ff];
__device__ u32 g_WbH[Ff * 5 * KDP];
__device__ u32 g_WbL[Ff * 5 * KDP];
__device__ float g_ms[Mm * Ff];
__device__ float g_mc[Mm * Ff];
__device__ float g_comb_part[Nn * 6 * 304];   // [n][chunk z][h*60+j]
__device__ float g_attscore[Nn];
__device__ float g_local[Mm * Nn];
__device__ float g_tn[Nn];
__device__ float g_cosdt[Nn];

__device__ __forceinline__ int safe_id(const int* p, int i) {
    int v = p[i];
    return v < 0 ? 0 : (v >= VOCAB ? VOCAB - 1 : v);
}
__device__ __forceinline__ u32 smem_to_u32(const void* p) {
    u32 a;
    asm("{ .reg .u64 t; cvta.to.shared.u64 t, %1; cvt.u32.u64 %0, t; }" : "=r"(a) : "l"(p));
    return a;
}
__device__ __forceinline__ void ldsm_x4(u32 addr, u32& r0, u32& r1, u32& r2, u32& r3) {
    asm volatile("ldmatrix.sync.aligned.m8n8.x4.shared.b16 {%0,%1,%2,%3}, [%4];"
                 : "=r"(r0), "=r"(r1), "=r"(r2), "=r"(r3) : "r"(addr));
}
__device__ __forceinline__ void mma_bf16(float* c, u32 a0, u32 a1, u32 a2, u32 a3,
                                         u32 b0, u32 b1) {
    asm volatile(
        "mma.sync.aligned.m16n8k16.row.col.f32.bf16.bf16.f32 "
        "{%0,%1,%2,%3}, {%4,%5,%6,%7}, {%8,%9}, {%0,%1,%2,%3};"
        : "+f"(c[0]), "+f"(c[1]), "+f"(c[2]), "+f"(c[3])
        : "r"(a0), "r"(a1), "r"(a2), "r"(a3), "r"(b0), "r"(b1));
}
__device__ __forceinline__ void split_pair(float a, float b, u32& hi, u32& lo) {
    __nv_bfloat16 ha = __float2bfloat16(a);
    __nv_bfloat16 hb = __float2bfloat16(b);
    __nv_bfloat16 la = __float2bfloat16(a - __bfloat162float(ha));
    __nv_bfloat16 lb = __float2bfloat16(b - __bfloat162float(hb));
    hi = ((u32)__bfloat16_as_ushort(hb) << 16) | (u32)__bfloat16_as_ushort(ha);
    lo = ((u32)__bfloat16_as_ushort(lb) << 16) | (u32)__bfloat16_as_ushort(la);
}

__device__ __forceinline__ float warp_sum(float v) {
#pragma unroll
    for (int o = 16; o; o >>= 1) v += __shfl_xor_sync(0xFFFFFFFFu, v, o);
    return v;
}
__device__ __forceinline__ float warp_max(float v) {
#pragma unroll
    for (int o = 16; o; o >>= 1) v = fmaxf(v, __shfl_xor_sync(0xFFFFFFFFu, v, o));
    return v;
}
__device__ __forceinline__ float r16_sum(float v) {
#pragma unroll
    for (int o = 8; o; o >>= 1) v += __shfl_xor_sync(0xFFFFu, v, o, 16);
    return v;
}
__device__ __forceinline__ float r16_max(float v) {
#pragma unroll
    for (int o = 8; o; o >>= 1) v = fmaxf(v, __shfl_xor_sync(0xFFFFu, v, o, 16));
    return v;
}
__device__ __forceinline__ float r16_min(float v) {
#pragma unroll
    for (int o = 8; o; o >>= 1) v = fminf(v, __shfl_xor_sync(0xFFFFu, v, o, 16));
    return v;
}

// ---------------- weight prep ----------------
__global__ void wprep_kernel(const float* __restrict__ Wms,
                             const float* __restrict__ Wmc) {
    int idx = blockIdx.x * blockDim.x + threadIdx.x;
    const int nW = Ff * 5 * KDP;
    if (idx < nW) {
        int f = idx / (5 * KDP);
        int r = idx - f * (5 * KDP);
        int tap = r / KDP;
        int dp = r - tap * KDP;
        int d = 2 * dp;
        float a = (d < Dd) ? Wmc[(size_t)f * Dd * 5 + d * 5 + tap] : 0.f;
        float b = (d + 1 < Dd) ? Wmc[(size_t)f * Dd * 5 + (d + 1) * 5 + tap] : 0.f;
        u32 hi, lo;
        split_pair(a, b, hi, lo);
        g_WbH[idx] = hi;
        g_WbL[idx] = lo;
    } else {
        int i = idx - nW;
        if (i < 2 * Dd * Ff) {
            int f = i % Ff;
            int rest = i / Ff;
            int d = rest % Dd;
            int k = rest / Dd;
            g_Wt_ms[i] = Wms[(size_t)f * Dd * 2 + d * 2 + k];
        }
    }
}

// ---------------- surface conv ----------------
__launch_bounds__(192)
__global__ void conv_ms_kernel(const int* __restrict__ ids,
                               const float* __restrict__ emb,
                               const float* __restrict__ bias) {
    const int m = blockIdx.x;
    const int tid = threadIdx.x;
    __shared__ float Xs[SURF_L * Dd];
    for (int i = tid; i < SURF_L * Dd; i += 192) {
        int l = i / Dd, d = i - l * Dd;
        Xs[i] = emb[(size_t)safe_id(ids, m * SURF_L + l) * Dd + d];
    }
    __syncthreads();
    float4 acc[3];
#pragma unroll
    for (int t = 0; t < 3; t++) acc[t] = make_float4(0.f, 0.f, 0.f, 0.f);
#pragma unroll
    for (int k = 0; k < 2; k++) {
        const float4* __restrict__ wp = (const float4*)(g_Wt_ms + (size_t)k * Dd * Ff) + tid;
        const float* __restrict__ xk = Xs + k * Dd;
        for (int d = 0; d < Dd; d++) {
            float4 w = wp[(size_t)d * (Ff / 4)];
#pragma unroll
            for (int t = 0; t < 3; t++) {
                float xv = xk[t * Dd + d];
                acc[t].x = fmaf(xv, w.x, acc[t].x);
                acc[t].y = fmaf(xv, w.y, acc[t].y);
                acc[t].z = fmaf(xv, w.z, acc[t].z);
                acc[t].w = fmaf(xv, w.w, acc[t].w);
            }
        }
    }
    float4 b4 = ((const float4*)bias)[tid];
    float4 s = make_float4(0.f, 0.f, 0.f, 0.f);
#pragma unroll
    for (int t = 0; t < 3; t++) {
        s.x += fmaxf(acc[t].x + b4.x, 0.f);
        s.y += fmaxf(acc[t].y + b4.y, 0.f);
        s.z += fmaxf(acc[t].z + b4.z, 0.f);
        s.w += fmaxf(acc[t].w + b4.w, 0.f);
    }
    s.x *= (1.f / 3.f); s.y *= (1.f / 3.f); s.z *= (1.f / 3.f); s.w *= (1.f / 3.f);
    ((float4*)(g_ms + (size_t)m * Ff))[tid] = s;
}

// ---------------- context conv via mma.sync (round-8 verbatim) ----------------
// CTA = 2 mentions x 128 f. Warp (mi, nh) computes 48 rows (3 m16) x 64 f (8 n8).
#define XHALF 31616              // 52*304*2 bytes per half per mention
#define XMEN (2 * XHALF)         // 63232 per mention (hi+lo)
#define WS_OFF (2 * XMEN)        // 126464
#define SMEM_CONV (WS_OFF + 128 * KD * 2)   // +77824 = 204288

__global__ void __launch_bounds__(128, 1)
conv_mma2_kernel(const int* __restrict__ ids,
                 const float* __restrict__ emb,
                 const float* __restrict__ bias) {
    extern __shared__ char smem[];
    const int tid = threadIdx.x;
    const int lane = tid & 31;
    const int w = tid >> 5;
    const int mi = w >> 1, nh = w & 1;
    const int mp = blockIdx.x;       // mention pair 0..31
    const int f0 = blockIdx.y * 128; // f-range

    for (int i = tid; i < 2 * 52 * KDP; i += 128) {
        int m2 = i / (52 * KDP);
        int rem = i - m2 * (52 * KDP);
        int row = rem / KDP;
        int dp = rem - row * KDP;
        int d = 2 * dp;
        float a = 0.f, b = 0.f;
        if (row < CTX_L) {
            const float* er = emb + (size_t)safe_id(ids, (mp * 2 + m2) * CTX_L + row) * Dd;
            if (d < Dd) a = er[d];
            if (d + 1 < Dd) b = er[d + 1];
        }
        u32 hi, lo;
        split_pair(a, b, hi, lo);
        ((u32*)(smem + m2 * XMEN))[row * KDP + dp] = hi;
        ((u32*)(smem + m2 * XMEN + XHALF))[row * KDP + dp] = lo;
    }

    const u32 sb = smem_to_u32(smem);
    const u32 xbase = sb + (u32)(mi * XMEN);
    const u32 wsb = sb + WS_OFF;

    const int a_r = lane & 15;
    const int a_k = (lane >> 4) << 3;
    const int b_n = ((lane >> 4) << 3) + (lane & 7);
    const int b_k = ((lane >> 3) & 1) << 3;

    float C[3][8][4];
#pragma unroll
    for (int mt = 0; mt < 3; mt++)
#pragma unroll
        for (int nt = 0; nt < 8; nt++)
#pragma unroll
            for (int j = 0; j < 4; j++) C[mt][nt][j] = 0.f;

    for (int half = 0; half < 2; half++) {
        const u32* __restrict__ wsrc = half ? g_WbL : g_WbH;
        for (int tap = 0; tap < 5; tap++) {
            __syncthreads();
            {
                const uint4* __restrict__ src = (const uint4*)wsrc;
                uint4* __restrict__ dst = (uint4*)(smem + WS_OFF);
                for (int i = tid; i < 128 * 38; i += 128) {
                    int fi = i / 38, c = i - fi * 38;
                    dst[i] = src[(size_t)(f0 + fi) * (5 * KDP / 4) + tap * 38 + c];
                }
            }
            __syncthreads();
            for (int ks = 0; ks < 19; ks++) {
                const int k0 = ks * 16;
                u32 Bf[8][2];
#pragma unroll
                for (int p = 0; p < 4; p++) {
                    u32 addr = wsb + (u32)(((nh * 64 + p * 16 + b_n) * KD + k0 + b_k) * 2);
                    ldsm_x4(addr, Bf[2 * p][0], Bf[2 * p][1], Bf[2 * p + 1][0], Bf[2 * p + 1][1]);
                }
#pragma unroll
                for (int mt = 0; mt < 3; mt++) {
                    u32 aoff = (u32)(((mt * 16 + tap + a_r) * KD + k0 + a_k) * 2);
                    u32 A0, A1, A2, A3;
                    ldsm_x4(xbase + aoff, A0, A1, A2, A3);
#pragma unroll
                    for (int nt = 0; nt < 8; nt++)
                        mma_bf16(C[mt][nt], A0, A1, A2, A3, Bf[nt][0], Bf[nt][1]);
                    if (half == 0) {
                        ldsm_x4(xbase + XHALF + aoff, A0, A1, A2, A3);
#pragma unroll
                        for (int nt = 0; nt < 8; nt++)
                            mma_bf16(C[mt][nt], A0, A1, A2, A3, Bf[nt][0], Bf[nt][1]);
                    }
                }
            }
        }
    }

    __syncthreads();
    float* stg = (float*)(smem + WS_OFF);  // [2][48][128]
#pragma unroll
    for (int mt = 0; mt < 3; mt++)
#pragma unroll
        for (int nt = 0; nt < 8; nt++) {
            int row = mt * 16 + (lane >> 2);
            int col = nh * 64 + nt * 8 + (lane & 3) * 2;
            float* base = stg + mi * 6144 + row * 128 + col;
            base[0] = C[mt][nt][0];
            base[1] = C[mt][nt][1];
            base[8 * 128] = C[mt][nt][2];
            base[8 * 128 + 1] = C[mt][nt][3];
        }
    __syncthreads();
    for (int idx = tid; idx < 256; idx += 128) {
        int m2 = idx >> 7, f = idx & 127;
        float b = bias[f0 + f];
        float s = 0.f;
        for (int t = 0; t < 46; t++) s += fmaxf(stg[m2 * 6144 + t * 128 + f] + b, 0.f);
        g_mc[(size_t)(mp * 2 + m2) * Ff + f0 + f] = s * (1.0f / 46.0f);
    }
}

// ---------------- cross attention: q chunked into 50-row blocks (round-9) ----------------
__global__ void __launch_bounds__(256, 2)
attn_kernel(const int* __restrict__ doc_ids,
            const int* __restrict__ body_ids,
            const float* __restrict__ emb) {
    const int n = blockIdx.x, h = blockIdx.y, z = blockIdx.z;
    const int dir = (z < 2) ? 0 : 1;
    const int q0 = (dir == 0 ? z : z - 2) * 50;
    const int Lk = dir == 0 ? BODY_L : DOC_L;
    extern __shared__ float sh[];
    float* qs = sh;                 // 50*60
    float* ks = qs + 50 * HD;       // Lk*60
    float* S = ks + Lk * HD;        // 50*Lk
    __shared__ float red[8][64];

    const int tid = threadIdx.x;    // 256
    const int* qsrc = (dir == 0) ? (doc_ids + q0) : (body_ids + n * BODY_L + q0);
    const int* ksrc = (dir == 0) ? (body_ids + n * BODY_L) : doc_ids;

    for (int i = tid; i < 50 * HD; i += 256) {
        int l = i / HD, j = i - l * HD;
        qs[i] = emb[(size_t)safe_id(qsrc, l) * Dd + h * HD + j];
    }
    for (int i = tid; i < Lk * HD; i += 256) {
        int l = i / HD, j = i - l * HD;
        ks[i] = emb[(size_t)safe_id(ksrc, l) * Dd + h * HD + j];
    }
    __syncthreads();

    const float scale = rsqrtf((float)HD);
    const float4* qs4 = (const float4*)qs;
    const float4* ks4 = (const float4*)ks;
    for (int idx = tid; idx < 50 * Lk; idx += 256) {
        int q = idx / Lk, k = idx - q * Lk;
        float4 a = make_float4(0.f, 0.f, 0.f, 0.f);
#pragma unroll
        for (int j = 0; j < 15; j++) {
            float4 qv = qs4[q * 15 + j];
            float4 kv = ks4[k * 15 + j];
            a.x = fmaf(qv.x, kv.x, a.x);
            a.y = fmaf(qv.y, kv.y, a.y);
            a.z = fmaf(qv.z, kv.z, a.z);
            a.w = fmaf(qv.w, kv.w, a.w);
        }
        S[idx] = (a.x + a.y + a.z + a.w) * scale;
    }
    __syncthreads();

    const int wid = tid >> 5, lane = tid & 31;
    for (int q = wid; q < 50; q += 8) {
        float* row = S + q * Lk;
        float mx = -1e30f;
        for (int k = lane; k < Lk; k += 32) mx = fmaxf(mx, row[k]);
        mx = warp_max(mx);
        float sum = 0.f;
        for (int k = lane; k < Lk; k += 32) {
            float e = expf(row[k] - mx);
            row[k] = e;
            sum += e;
        }
        sum = warp_sum(sum);
        float inv = 1.f / sum;
        for (int k = lane; k < Lk; k += 32) row[k] *= inv;
    }
    __syncthreads();

    if (lane < 30) {
        const float2* ks2 = (const float2*)ks;
        float2 mx = make_float2(-1e30f, -1e30f);
        for (int q = wid; q < 50; q += 8) {
            const float* row = S + q * Lk;
            float2 o0 = make_float2(0.f, 0.f), o1 = make_float2(0.f, 0.f);
            for (int k = 0; k < Lk; k += 2) {
                float p0 = row[k], p1 = row[k + 1];
                float2 v0 = ks2[k * 30 + lane];
                float2 v1 = ks2[(k + 1) * 30 + lane];
                o0.x = fmaf(p0, v0.x, o0.x);
                o0.y = fmaf(p0, v0.y, o0.y);
                o1.x = fmaf(p1, v1.x, o1.x);
                o1.y = fmaf(p1, v1.y, o1.y);
            }
            mx.x = fmaxf(mx.x, o0.x + o1.x);
            mx.y = fmaxf(mx.y, o0.y + o1.y);
        }
        red[wid][2 * lane] = mx.x;
        red[wid][2 * lane + 1] = mx.y;
    }
    __syncthreads();
    if (tid < 60) {
        float mxv = -1e30f;
#pragma unroll
        for (int g = 0; g < 8; g++) mxv = fmaxf(mxv, red[g][tid]);
        g_comb_part[(n * 6 + z) * 304 + h * HD + tid] = mxv;
    }
}

// ---------------- attention MLP (combines chunk maxes) ----------------
__global__ void attmlp_kernel(const float* __restrict__ W1,
                              const float* __restrict__ b1,
                              const float* __restrict__ W2,
                              const float* __restrict__ b2) {
    const int n = blockIdx.x;
    __shared__ float cb[600];
    __shared__ float partial[10];
    const int tid = threadIdx.x;  // 320
    const float* part = g_comb_part + n * 6 * 304;
    for (int i = tid; i < 600; i += 320) {
        float v;
        if (i < 300) {
            v = fmaxf(part[0 * 304 + i], part[1 * 304 + i]);
        } else {
            int j = i - 300;
            v = fmaxf(fmaxf(part[2 * 304 + j], part[3 * 304 + j]),
                      fmaxf(part[4 * 304 + j], part[5 * 304 + j]));
        }
        cb[i] = v;
    }
    __syncthreads();
    float v = 0.f;
    if (tid < 300) {
        float a0 = b1[tid], a1 = 0.f, a2 = 0.f, a3 = 0.f;
        for (int i = 0; i < 600; i += 4) {
            a0 = fmaf(cb[i], W1[i * 300 + tid], a0);
            a1 = fmaf(cb[i + 1], W1[(i + 1) * 300 + tid], a1);
            a2 = fmaf(cb[i + 2], W1[(i + 2) * 300 + tid], a2);
            a3 = fmaf(cb[i + 3], W1[(i + 3) * 300 + tid], a3);
        }
        float a = (a0 + a1) + (a2 + a3);
        a = fmaxf(a, 0.f);
        v = a * W2[tid];
    }
    v = warp_sum(v);
    if ((tid & 31) == 0) partial[tid >> 5] = v;
    __syncthreads();
    if (tid == 0) {
        float s = 0.f;
        for (int w = 0; w < 10; w++) s += partial[w];
        s += b2[0];
        g_attscore[n] = 1.f / (1.f + expf(-s));
    }
}

// ---------------- LocalCtxAttRanker ----------------
__global__ void localctx_kernel(const int* __restrict__ cand_ids,
                                const int* __restrict__ ctx_ids,
                                const float* __restrict__ emb) {
    const int m = blockIdx.x;
    extern __shared__ float sh[];
    float* cs = sh;
    float* xs = cs + Nn * Dd;
    float* tok = xs + CTX_L * Dd;
    float* p = tok + Nn * CTX_L;
    float* ctxv = p + CTX_L;
    const int tid = threadIdx.x;  // 256

    for (int i = tid; i < Nn * Dd; i += 256) {
        int n = i / Dd, d = i - n * Dd;
        cs[i] = emb[(size_t)safe_id(cand_ids, m * Nn + n) * Dd + d];
    }
    for (int i = tid; i < CTX_L * Dd; i += 256) {
        int t = i / Dd, d = i - t * Dd;
        xs[i] = emb[(size_t)safe_id(ctx_ids, m * CTX_L + t) * Dd + d];
    }
    __syncthreads();

    const float4* cs4 = (const float4*)cs;
    const float4* xs4 = (const float4*)xs;
    for (int idx = tid; idx < Nn * CTX_L; idx += 256) {
        int n = idx / CTX_L, t = idx - n * CTX_L;
        float4 a = make_float4(0.f, 0.f, 0.f, 0.f);
#pragma unroll 5
        for (int j = 0; j < 75; j++) {
            float4 cv = cs4[n * 75 + j];
            float4 xv = xs4[t * 75 + j];
            a.x = fmaf(cv.x, xv.x, a.x);
            a.y = fmaf(cv.y, xv.y, a.y);
            a.z = fmaf(cv.z, xv.z, a.z);
            a.w = fmaf(cv.w, xv.w, a.w);
        }
        tok[idx] = (a.x + a.y) + (a.z + a.w);
    }
    __syncthreads();
    if (tid < CTX_L) {
        float mx = -1e30f;
        for (int n = 0; n < Nn; n++) mx = fmaxf(mx, tok[n * CTX_L + tid]);
        p[tid] = mx;
    }
    __syncthreads();
    if (tid < 32) {
        float mx = -1e30f;
        for (int t = tid; t < CTX_L; t += 32) mx = fmaxf(mx, p[t]);
        mx = warp_max(mx);
        float sum = 0.f;
        for (int t = tid; t < CTX_L; t += 32) {
            float e = expf(p[t] - mx);
            p[t] = e;
            sum += e;
        }
        sum = warp_sum(sum);
        float inv = 1.f / sum;
        for (int t = tid; t < CTX_L; t += 32) p[t] *= inv;
    }
    __syncthreads();
    for (int d = tid; d < Dd; d += 256) {
        float s = 0.f;
        for (int t = 0; t < CTX_L; t++) s = fmaf(p[t], xs[t * Dd + d], s);
        ctxv[d] = s;
    }
    __syncthreads();
    const int wid = tid >> 5, lane = tid & 31;
    for (int n = wid; n < Nn; n += 8) {
        float s = 0.f;
        for (int d = lane; d < Dd; d += 32) s = fmaf(cs[n * Dd + d], ctxv[d], s);
        s = warp_sum(s);
        if (lane == 0) g_local[m * Nn + n] = s;
    }
}

// ---------------- prep ----------------
__global__ void prep_kernel(const float* __restrict__ title,
                            const float* __restrict__ md) {
    const int w = threadIdx.x >> 5, lane = threadIdx.x & 31;
    float st2 = 0.f, smt = 0.f, sm2 = 0.f;
    for (int j = lane; j < Ff; j += 32) {
        float t = title[w * Ff + j];
        float mv = md[j];
        st2 = fmaf(t, t, st2);
        smt = fmaf(t, mv, smt);
        sm2 = fmaf(mv, mv, sm2);
    }
    st2 = warp_sum(st2);
    smt = warp_sum(smt);
    sm2 = warp_sum(sm2);
    if (lane == 0) {
        float tnv = sqrtf(st2);
        g_tn[w] = tnv;
        g_cosdt[w] = smt / (fmaxf(sqrtf(sm2), 1e-6f) * fmaxf(tnv, 1e-6f));
    }
}

// ---------------- final ----------------
__global__ void final_kernel(const float* __restrict__ title,
                             const float* __restrict__ prior,
                             const float* __restrict__ hand,
                             const float* __restrict__ w7,
                             const float* __restrict__ b7,
                             float* __restrict__ out) {
    const int m = blockIdx.x;
    const int tid = threadIdx.x;  // 256
    const int wid = tid >> 5, lane = tid & 31;
    __shared__ float nms_s, nmc_s;
    __shared__ float dst[Nn], dct[Nn], sc[Nn];

    if (wid == 0) {
        float s = 0.f;
        for (int j = lane; j < Ff; j += 32) {
            float v = g_ms[m * Ff + j];
            s = fmaf(v, v, s);
        }
        s = warp_sum(s);
        if (lane == 0) nms_s = fmaxf(sqrtf(s), 1e-6f);
    }
    if (wid == 1) {
        float s = 0.f;
        for (int j = lane; j < Ff; j += 32) {
            float v = g_mc[m * Ff + j];
            s = fmaf(v, v, s);
        }
        s = warp_sum(s);
        if (lane == 0) nmc_s = fmaxf(sqrtf(s), 1e-6f);
    }
    for (int item = wid; item < 32; item += 8) {
        int n = item & 15;
        int which = item >> 4;
        const float* a = which ? (g_mc + m * Ff) : (g_ms + m * Ff);
        float s = 0.f;
        for (int j = lane; j < Ff; j += 32) s = fmaf(a[j], title[n * Ff + j], s);
        s = warp_sum(s);
        if (lane == 0) {
            if (which) dct[n] = s;
            else dst[n] = s;
        }
    }
    __syncthreads();

    if (tid < Nn) {
        int n = tid;
        float tc = fmaxf(g_tn[n], 1e-6f);
        float cst = dst[n] / (nms_s * tc);
        float cct = dct[n] / (nmc_s * tc);
        float s = b7[0];
        s = fmaf(w7[0], hand[n], s);
        s = fmaf(w7[1], prior[n], s);
        s = fmaf(w7[2], g_local[m * Nn + n], s);
        s = fmaf(w7[3], g_attscore[n], s);
        s = fmaf(w7[4], cst, s);
        s = fmaf(w7[5], g_cosdt[n], s);
        s = fmaf(w7[6], cct, s);
        sc[n] = s;
    }
    __syncthreads();
    if (tid < Nn) {
        float x = sc[tid];
        float mu = r16_sum(x) * (1.f / 16.f);
        float dv = x - mu;
        float var = r16_sum(dv * dv) * (1.f / 15.f);
        float z = dv / sqrtf(var);
        out[m * Nn + tid] = z;
        float zmax = r16_max(z);
        float zmin = r16_min(z);
        float e = expf(z - zmax);
        float es = r16_sum(e);
        out[Mm * Nn + m * Nn + tid] = e / es;
        float u = (z + 1.f - zmin) / (zmax - zmin);
        float us = r16_sum(u);
        out[2 * Mm * Nn + m * Nn + tid] = u / us;
    }
}

// ---------------- launch ----------------
extern "C" void kernel_launch(void* const* d_in, const int* in_sizes, int n_in,
                              void* d_out, int out_size) {
    int e = -1;
    for (int i = 0; i < n_in; i++) {
        if (in_sizes[i] == VOCAB * Dd) { e = i; break; }
    }
    if (e < 0) e = 14;

    const int* mention_vec  = (const int*)d_in[e - 11];
    const int* context_vec  = (const int*)d_in[e - 10];
    const int* doc_vec      = (const int*)d_in[e - 9];
    const float* title      = (const float*)d_in[e - 8];
    const int* body_vec     = (const int*)d_in[e - 7];
    const float* prior      = (const float*)d_in[e - 5];
    const int* men2cands    = (const int*)d_in[e - 4];
    const int* contexts_ids = (const int*)d_in[e - 3];
    const float* hand       = (const float*)d_in[e - 2];
    const float* bert       = (const float*)d_in[e - 1];
    const float* emb        = (const float*)d_in[e];
    const float* Wms        = (const float*)d_in[e + 1];
    const float* bms        = (const float*)d_in[e + 2];
    const float* Wmc        = (const float*)d_in[e + 3];
    const float* bmc        = (const float*)d_in[e + 4];
    const float* w7         = (const float*)d_in[e + 5];
    const float* b7         = (const float*)d_in[e + 6];
    const float* W1         = (const float*)d_in[e + 7];
    const float* b1         = (const float*)d_in[e + 8];
    const float* W2         = (const float*)d_in[e + 9];
    const float* b2         = (const float*)d_in[e + 10];
    float* out = (float*)d_out;

    static bool s_init = false;
    static cudaStream_t s0, s1, s2;
    static cudaEvent_t evF, ev0, ev1, ev2;
    if (!s_init) {
        cudaStreamCreateWithFlags(&s0, cudaStreamNonBlocking);
        cudaStreamCreateWithFlags(&s1, cudaStreamNonBlocking);
        cudaStreamCreateWithFlags(&s2, cudaStreamNonBlocking);
        cudaEventCreateWithFlags(&evF, cudaEventDisableTiming);
        cudaEventCreateWithFlags(&ev0, cudaEventDisableTiming);
        cudaEventCreateWithFlags(&ev1, cudaEventDisableTiming);
        cudaEventCreateWithFlags(&ev2, cudaEventDisableTiming);
        s_init = true;
    }

    cudaFuncSetAttribute(attn_kernel, cudaFuncAttributeMaxDynamicSharedMemorySize, 100000);
    cudaFuncSetAttribute(localctx_kernel, cudaFuncAttributeMaxDynamicSharedMemorySize, 84000);
    cudaFuncSetAttribute(conv_mma2_kernel, cudaFuncAttributeMaxDynamicSharedMemorySize, SMEM_CONV);

    cudaEventRecord(evF, 0);
    cudaStreamWaitEvent(s0, evF, 0);
    cudaStreamWaitEvent(s1, evF, 0);
    cudaStreamWaitEvent(s2, evF, 0);

    // s0: weight prep -> convs (round-8 conv)
    wprep_kernel<<<(Ff * 5 * KDP + 2 * Dd * Ff + 255) / 256, 256, 0, s0>>>(Wms, Wmc);
    conv_ms_kernel<<<Mm, 192, 0, s0>>>(mention_vec, emb, bms);
    conv_mma2_kernel<<<dim3(Mm / 2, Ff / 128), 128, SMEM_CONV, s0>>>(context_vec, emb, bmc);
    cudaEventRecord(ev0, s0);

    // s1: cross attention (chunked, round-9) + MLP score
    attn_kernel<<<dim3(Nn, NH, 6), 256, 100000, s1>>>(doc_vec, body_vec, emb);
    attmlp_kernel<<<Nn, 320, 0, s1>>>(W1, b1, W2, b2);
    cudaEventRecord(ev1, s1);

    // s2: local context ranker + title prep
    localctx_kernel<<<Mm, 256, 84000, s2>>>(men2cands, contexts_ids, emb);
    prep_kernel<<<1, 512, 0, s2>>>(title, bert);
    cudaEventRecord(ev2, s2);

    cudaStreamWaitEvent(0, ev0, 0);
    cudaStreamWaitEvent(0, ev1, 0);
    cudaStreamWaitEvent(0, ev2, 0);

    final_kernel<<<Mm, 256>>>(title, prior, hand, w7, b7, out);
}

// round 12
// speedup vs baseline: 1.7640x; 1.2278x over previous
#include <cuda_runtime.h>
#include <cuda_bf16.h>
#include <math.h>

#define Mm 64
#define Nn 16
#define Dd 300
#define Ff 768
#define VOCAB 100000
#define SURF_L 4
#define CTX_L 50
#define DOC_L 100
#define BODY_L 200
#define HD 60
#define NH 5

#define KD 304               // padded d per tap
#define KDP (KD / 2)         // u32 pairs per tap row = 152

typedef unsigned long long u64;
typedef unsigned int u32;

// ---------------- scratch (__device__ globals, no allocation) ----------------
__device__ float g_Wt_ms[2 * Dd * Ff];
__device__ u32 g_WbH[Ff * 5 * KDP + 32];   // +32 pad: kh1 stage reads 8 uint4 past end
__device__ u32 g_WbL[Ff * 5 * KDP + 32];
__device__ float g_ms[Mm * Ff];
__device__ float g_mc[Mm * Ff];
__device__ float g_comb_part[Nn * 6 * 304];
__device__ float g_attscore[Nn];
__device__ float g_local[Mm * Nn];
__device__ float g_tn[Nn];
__device__ float g_cosdt[Nn];

__device__ __forceinline__ int safe_id(const int* p, int i) {
    int v = p[i];
    return v < 0 ? 0 : (v >= VOCAB ? VOCAB - 1 : v);
}
__device__ __forceinline__ u32 smem_to_u32(const void* p) {
    u32 a;
    asm("{ .reg .u64 t; cvta.to.shared.u64 t, %1; cvt.u32.u64 %0, t; }" : "=r"(a) : "l"(p));
    return a;
}
__device__ __forceinline__ void ldsm_x4(u32 addr, u32& r0, u32& r1, u32& r2, u32& r3) {
    asm volatile("ldmatrix.sync.aligned.m8n8.x4.shared.b16 {%0,%1,%2,%3}, [%4];"
                 : "=r"(r0), "=r"(r1), "=r"(r2), "=r"(r3) : "r"(addr));
}
__device__ __forceinline__ void mma_bf16(float* c, u32 a0, u32 a1, u32 a2, u32 a3,
                                         u32 b0, u32 b1) {
    asm volatile(
        "mma.sync.aligned.m16n8k16.row.col.f32.bf16.bf16.f32 "
        "{%0,%1,%2,%3}, {%4,%5,%6,%7}, {%8,%9}, {%0,%1,%2,%3};"
        : "+f"(c[0]), "+f"(c[1]), "+f"(c[2]), "+f"(c[3])
        : "r"(a0), "r"(a1), "r"(a2), "r"(a3), "r"(b0), "r"(b1));
}
__device__ __forceinline__ void cp_async16(u32 dst, const void* src) {
    asm volatile("cp.async.cg.shared.global [%0], [%1], 16;" :: "r"(dst), "l"(src));
}
__device__ __forceinline__ void split_pair(float a, float b, u32& hi, u32& lo) {
    __nv_bfloat16 ha = __float2bfloat16(a);
    __nv_bfloat16 hb = __float2bfloat16(b);
    __nv_bfloat16 la = __float2bfloat16(a - __bfloat162float(ha));
    __nv_bfloat16 lb = __float2bfloat16(b - __bfloat162float(hb));
    hi = ((u32)__bfloat16_as_ushort(hb) << 16) | (u32)__bfloat16_as_ushort(ha);
    lo = ((u32)__bfloat16_as_ushort(lb) << 16) | (u32)__bfloat16_as_ushort(la);
}

__device__ __forceinline__ float warp_sum(float v) {
#pragma unroll
    for (int o = 16; o; o >>= 1) v += __shfl_xor_sync(0xFFFFFFFFu, v, o);
    return v;
}
__device__ __forceinline__ float warp_max(float v) {
#pragma unroll
    for (int o = 16; o; o >>= 1) v = fmaxf(v, __shfl_xor_sync(0xFFFFFFFFu, v, o));
    return v;
}
__device__ __forceinline__ float r16_sum(float v) {
#pragma unroll
    for (int o = 8; o; o >>= 1) v += __shfl_xor_sync(0xFFFFu, v, o, 16);
    return v;
}
__device__ __forceinline__ float r16_max(float v) {
#pragma unroll
    for (int o = 8; o; o >>= 1) v = fmaxf(v, __shfl_xor_sync(0xFFFFu, v, o, 16));
    return v;
}
__device__ __forceinline__ float r16_min(float v) {
#pragma unroll
    for (int o = 8; o; o >>= 1) v = fminf(v, __shfl_xor_sync(0xFFFFu, v, o, 16));
    return v;
}

// ---------------- weight prep ----------------
__global__ void wprep_kernel(const float* __restrict__ Wms,
                             const float* __restrict__ Wmc) {
    int idx = blockIdx.x * blockDim.x + threadIdx.x;
    const int nW = Ff * 5 * KDP;
    if (idx < nW) {
        int f = idx / (5 * KDP);
        int r = idx - f * (5 * KDP);
        int tap = r / KDP;
        int dp = r - tap * KDP;
        int d = 2 * dp;
        float a = (d < Dd) ? Wmc[(size_t)f * Dd * 5 + d * 5 + tap] : 0.f;
        float b = (d + 1 < Dd) ? Wmc[(size_t)f * Dd * 5 + (d + 1) * 5 + tap] : 0.f;
        u32 hi, lo;
        split_pair(a, b, hi, lo);
        g_WbH[idx] = hi;
        g_WbL[idx] = lo;
    } else {
        int i = idx - nW;
        if (i < 2 * Dd * Ff) {
            int f = i % Ff;
            int rest = i / Ff;
            int d = rest % Dd;
            int k = rest / Dd;
            g_Wt_ms[i] = Wms[(size_t)f * Dd * 2 + d * 2 + k];
        }
    }
}

// ---------------- surface conv ----------------
__launch_bounds__(192)
__global__ void conv_ms_kernel(const int* __restrict__ ids,
                               const float* __restrict__ emb,
                               const float* __restrict__ bias) {
    const int m = blockIdx.x;
    const int tid = threadIdx.x;
    __shared__ float Xs[SURF_L * Dd];
    for (int i = tid; i < SURF_L * Dd; i += 192) {
        int l = i / Dd, d = i - l * Dd;
        Xs[i] = emb[(size_t)safe_id(ids, m * SURF_L + l) * Dd + d];
    }
    __syncthreads();
    float4 acc[3];
#pragma unroll
    for (int t = 0; t < 3; t++) acc[t] = make_float4(0.f, 0.f, 0.f, 0.f);
#pragma unroll
    for (int k = 0; k < 2; k++) {
        const float4* __restrict__ wp = (const float4*)(g_Wt_ms + (size_t)k * Dd * Ff) + tid;
        const float* __restrict__ xk = Xs + k * Dd;
        for (int d = 0; d < Dd; d++) {
            float4 w = wp[(size_t)d * (Ff / 4)];
#pragma unroll
            for (int t = 0; t < 3; t++) {
                float xv = xk[t * Dd + d];
                acc[t].x = fmaf(xv, w.x, acc[t].x);
                acc[t].y = fmaf(xv, w.y, acc[t].y);
                acc[t].z = fmaf(xv, w.z, acc[t].z);
                acc[t].w = fmaf(xv, w.w, acc[t].w);
            }
        }
    }
    float4 b4 = ((const float4*)bias)[tid];
    float4 s = make_float4(0.f, 0.f, 0.f, 0.f);
#pragma unroll
    for (int t = 0; t < 3; t++) {
        s.x += fmaxf(acc[t].x + b4.x, 0.f);
        s.y += fmaxf(acc[t].y + b4.y, 0.f);
        s.z += fmaxf(acc[t].z + b4.z, 0.f);
        s.w += fmaxf(acc[t].w + b4.w, 0.f);
    }
    s.x *= (1.f / 3.f); s.y *= (1.f / 3.f); s.z *= (1.f / 3.f); s.w *= (1.f / 3.f);
    ((float4*)(g_ms + (size_t)m * Ff))[tid] = s;
}

// ---------------- context conv: mma.sync, 256 thr, cp.async double-buffered W ----------------
// CTA = 2 mentions x 128 f. Warp (mi, nq): 48 rows (3 m16) x 32 f (4 n8).
// 20 stages: (Whalf 2) x (tap 5) x (kh 2); slab = [128 f][160 elems] per stage.
#define XHALF 31616              // 52*304*2 bytes per half per mention
#define XMEN (2 * XHALF)         // 63232 per mention (hi+lo)
#define WS0 126464
#define WSLAB 40960              // 128 * 160 elems * 2B
#define WS1 (WS0 + WSLAB)
#define SMEM_CONV (WS1 + WSLAB)  // 208384

__global__ void __launch_bounds__(256, 1)
conv_mma2_kernel(const int* __restrict__ ids,
                 const float* __restrict__ emb,
                 const float* __restrict__ bias) {
    extern __shared__ char smem[];
    const int tid = threadIdx.x;
    const int lane = tid & 31;
    const int w = tid >> 5;
    const int mi = w >> 2, nq = w & 3;   // 8 warps: mention x 32-f quarter
    const int mp = blockIdx.x;           // mention pair 0..31
    const int f0 = blockIdx.y * 128;     // f-range

    const u32 sb = smem_to_u32(smem);

    // ---- issue W stage s into buffer s&1 via cp.async (10 uint4 per thread)
    auto stage_issue = [&](int s) {
        int half = s / 10, rem = s - half * 10;
        int tap = rem >> 1, kh = rem & 1;
        const u32* src = half ? g_WbL : g_WbH;
        u32 dst = sb + (u32)((s & 1) ? WS1 : WS0);
        for (int i = tid; i < 128 * 20; i += 256) {
            int row = i / 20, c = i - row * 20;
            const void* g = src + (size_t)(((f0 + row) * 5 + tap) * 38 + kh * 20 + c) * 4;
            cp_async16(dst + (u32)i * 16, g);
        }
    };

    // ---- X gather + hi/lo split (plain stores)
    for (int i = tid; i < 2 * 52 * KDP; i += 256) {
        int m2 = i / (52 * KDP);
        int rem = i - m2 * (52 * KDP);
        int row = rem / KDP;
        int dp = rem - row * KDP;
        int d = 2 * dp;
        float a = 0.f, b = 0.f;
        if (row < CTX_L) {
            const float* er = emb + (size_t)safe_id(ids, (mp * 2 + m2) * CTX_L + row) * Dd;
            if (d < Dd) a = er[d];
            if (d + 1 < Dd) b = er[d + 1];
        }
        u32 hi, lo;
        split_pair(a, b, hi, lo);
        ((u32*)(smem + m2 * XMEN))[row * KDP + dp] = hi;
        ((u32*)(smem + m2 * XMEN + XHALF))[row * KDP + dp] = lo;
    }

    const u32 xbase = sb + (u32)(mi * XMEN);
    const int a_r = lane & 15;
    const int a_k = (lane >> 4) << 3;
    const int b_n = ((lane >> 4) << 3) + (lane & 7);
    const int b_k = ((lane >> 3) & 1) << 3;

    float C[3][4][4];
#pragma unroll
    for (int mt = 0; mt < 3; mt++)
#pragma unroll
        for (int nt = 0; nt < 4; nt++)
#pragma unroll
            for (int j = 0; j < 4; j++) C[mt][nt][j] = 0.f;

    // prologue: stage 0 in flight; X must be visible before compute
    stage_issue(0);
    asm volatile("cp.async.commit_group;" ::: "memory");
    __syncthreads();

    for (int s = 0; s < 20; s++) {
        if (s + 1 < 20) stage_issue(s + 1);
        asm volatile("cp.async.commit_group;" ::: "memory");
        asm volatile("cp.async.wait_group 1;" ::: "memory");
        __syncthreads();

        const int half = s / 10, rem = s - half * 10;
        const int tap = rem >> 1, kh = rem & 1;
        const u32 buf = sb + (u32)((s & 1) ? WS1 : WS0);
        const int nks = kh ? 9 : 10;
        const int xk0 = kh ? 160 : 0;
        for (int ks = 0; ks < nks; ks++) {
            const int k0 = ks * 16;
            u32 Bf[4][2];
#pragma unroll
            for (int p = 0; p < 2; p++) {
                u32 addr = buf + (u32)(((nq * 32 + p * 16 + b_n) * 160 + k0 + b_k) * 2);
                ldsm_x4(addr, Bf[2 * p][0], Bf[2 * p][1], Bf[2 * p + 1][0], Bf[2 * p + 1][1]);
            }
#pragma unroll
            for (int mt = 0; mt < 3; mt++) {
                u32 aoff = (u32)(((mt * 16 + tap + a_r) * KD + xk0 + k0 + a_k) * 2);
                u32 A0, A1, A2, A3;
                ldsm_x4(xbase + aoff, A0, A1, A2, A3);
#pragma unroll
                for (int nt = 0; nt < 4; nt++)
                    mma_bf16(C[mt][nt], A0, A1, A2, A3, Bf[nt][0], Bf[nt][1]);
                if (half == 0) {
                    ldsm_x4(xbase + XHALF + aoff, A0, A1, A2, A3);
#pragma unroll
                    for (int nt = 0; nt < 4; nt++)
                        mma_bf16(C[mt][nt], A0, A1, A2, A3, Bf[nt][0], Bf[nt][1]);
                }
            }
        }
        __syncthreads();
    }

    // ---- epilogue: stage C [2][48][128], bias+relu+sum over t
    float* stg = (float*)(smem + WS0);
#pragma unroll
    for (int mt = 0; mt < 3; mt++)
#pragma unroll
        for (int nt = 0; nt < 4; nt++) {
            int row = mt * 16 + (lane >> 2);
            int col = nq * 32 + nt * 8 + (lane & 3) * 2;
            float* base = stg + mi * 6144 + row * 128 + col;
            base[0] = C[mt][nt][0];
            base[1] = C[mt][nt][1];
            base[8 * 128] = C[mt][nt][2];
            base[8 * 128 + 1] = C[mt][nt][3];
        }
    __syncthreads();
    {
        int m2 = tid >> 7, f = tid & 127;
        float b = bias[f0 + f];
        float s = 0.f;
        for (int t = 0; t < 46; t++) s += fmaxf(stg[m2 * 6144 + t * 128 + f] + b, 0.f);
        g_mc[(size_t)(mp * 2 + m2) * Ff + f0 + f] = s * (1.0f / 46.0f);
    }
}

// ---------------- cross attention: q chunked (round-9/10 verbatim) ----------------
__global__ void __launch_bounds__(256, 2)
attn_kernel(const int* __restrict__ doc_ids,
            const int* __restrict__ body_ids,
            const float* __restrict__ emb) {
    const int n = blockIdx.x, h = blockIdx.y, z = blockIdx.z;
    const int dir = (z < 2) ? 0 : 1;
    const int q0 = (dir == 0 ? z : z - 2) * 50;
    const int Lk = dir == 0 ? BODY_L : DOC_L;
    extern __shared__ float sh[];
    float* qs = sh;
    float* ks = qs + 50 * HD;
    float* S = ks + Lk * HD;
    __shared__ float red[8][64];

    const int tid = threadIdx.x;
    const int* qsrc = (dir == 0) ? (doc_ids + q0) : (body_ids + n * BODY_L + q0);
    const int* ksrc = (dir == 0) ? (body_ids + n * BODY_L) : doc_ids;

    for (int i = tid; i < 50 * HD; i += 256) {
        int l = i / HD, j = i - l * HD;
        qs[i] = emb[(size_t)safe_id(qsrc, l) * Dd + h * HD + j];
    }
    for (int i = tid; i < Lk * HD; i += 256) {
        int l = i / HD, j = i - l * HD;
        ks[i] = emb[(size_t)safe_id(ksrc, l) * Dd + h * HD + j];
    }
    __syncthreads();

    const float scale = rsqrtf((float)HD);
    const float4* qs4 = (const float4*)qs;
    const float4* ks4 = (const float4*)ks;
    for (int idx = tid; idx < 50 * Lk; idx += 256) {
        int q = idx / Lk, k = idx - q * Lk;
        float4 a = make_float4(0.f, 0.f, 0.f, 0.f);
#pragma unroll
        for (int j = 0; j < 15; j++) {
            float4 qv = qs4[q * 15 + j];
            float4 kv = ks4[k * 15 + j];
            a.x = fmaf(qv.x, kv.x, a.x);
            a.y = fmaf(qv.y, kv.y, a.y);
            a.z = fmaf(qv.z, kv.z, a.z);
            a.w = fmaf(qv.w, kv.w, a.w);
        }
        S[idx] = (a.x + a.y + a.z + a.w) * scale;
    }
    __syncthreads();

    const int wid = tid >> 5, lane = tid & 31;
    for (int q = wid; q < 50; q += 8) {
        float* row = S + q * Lk;
        float mx = -1e30f;
        for (int k = lane; k < Lk; k += 32) mx = fmaxf(mx, row[k]);
        mx = warp_max(mx);
        float sum = 0.f;
        for (int k = lane; k < Lk; k += 32) {
            float e = expf(row[k] - mx);
            row[k] = e;
            sum += e;
        }
        sum = warp_sum(sum);
        float inv = 1.f / sum;
        for (int k = lane; k < Lk; k += 32) row[k] *= inv;
    }
    __syncthreads();

    if (lane < 30) {
        const float2* ks2 = (const float2*)ks;
        float2 mx = make_float2(-1e30f, -1e30f);
        for (int q = wid; q < 50; q += 8) {
            const float* row = S + q * Lk;
            float2 o0 = make_float2(0.f, 0.f), o1 = make_float2(0.f, 0.f);
            for (int k = 0; k < Lk; k += 2) {
                float p0 = row[k], p1 = row[k + 1];
                float2 v0 = ks2[k * 30 + lane];
                float2 v1 = ks2[(k + 1) * 30 + lane];
                o0.x = fmaf(p0, v0.x, o0.x);
                o0.y = fmaf(p0, v0.y, o0.y);
                o1.x = fmaf(p1, v1.x, o1.x);
                o1.y = fmaf(p1, v1.y, o1.y);
            }
            mx.x = fmaxf(mx.x, o0.x + o1.x);
            mx.y = fmaxf(mx.y, o0.y + o1.y);
        }
        red[wid][2 * lane] = mx.x;
        red[wid][2 * lane + 1] = mx.y;
    }
    __syncthreads();
    if (tid < 60) {
        float mxv = -1e30f;
#pragma unroll
        for (int g = 0; g < 8; g++) mxv = fmaxf(mxv, red[g][tid]);
        g_comb_part[(n * 6 + z) * 304 + h * HD + tid] = mxv;
    }
}

// ---------------- attention MLP ----------------
__global__ void attmlp_kernel(const float* __restrict__ W1,
                              const float* __restrict__ b1,
                              const float* __restrict__ W2,
                              const float* __restrict__ b2) {
    const int n = blockIdx.x;
    __shared__ float cb[600];
    __shared__ float partial[10];
    const int tid = threadIdx.x;  // 320
    const float* part = g_comb_part + n * 6 * 304;
    for (int i = tid; i < 600; i += 320) {
        float v;
        if (i < 300) {
            v = fmaxf(part[0 * 304 + i], part[1 * 304 + i]);
        } else {
            int j = i - 300;
            v = fmaxf(fmaxf(part[2 * 304 + j], part[3 * 304 + j]),
                      fmaxf(part[4 * 304 + j], part[5 * 304 + j]));
        }
        cb[i] = v;
    }
    __syncthreads();
    float v = 0.f;
    if (tid < 300) {
        float a0 = b1[tid], a1 = 0.f, a2 = 0.f, a3 = 0.f;
        for (int i = 0; i < 600; i += 4) {
            a0 = fmaf(cb[i], W1[i * 300 + tid], a0);
            a1 = fmaf(cb[i + 1], W1[(i + 1) * 300 + tid], a1);
            a2 = fmaf(cb[i + 2], W1[(i + 2) * 300 + tid], a2);
            a3 = fmaf(cb[i + 3], W1[(i + 3) * 300 + tid], a3);
        }
        float a = (a0 + a1) + (a2 + a3);
        a = fmaxf(a, 0.f);
        v = a * W2[tid];
    }
    v = warp_sum(v);
    if ((tid & 31) == 0) partial[tid >> 5] = v;
    __syncthreads();
    if (tid == 0) {
        float s = 0.f;
        for (int w = 0; w < 10; w++) s += partial[w];
        s += b2[0];
        g_attscore[n] = 1.f / (1.f + expf(-s));
    }
}

// ---------------- LocalCtxAttRanker ----------------
__global__ void localctx_kernel(const int* __restrict__ cand_ids,
                                const int* __restrict__ ctx_ids,
                                const float* __restrict__ emb) {
    const int m = blockIdx.x;
    extern __shared__ float sh[];
    float* cs = sh;
    float* xs = cs + Nn * Dd;
    float* tok = xs + CTX_L * Dd;
    float* p = tok + Nn * CTX_L;
    float* ctxv = p + CTX_L;
    const int tid = threadIdx.x;  // 256

    for (int i = tid; i < Nn * Dd; i += 256) {
        int n = i / Dd, d = i - n * Dd;
        cs[i] = emb[(size_t)safe_id(cand_ids, m * Nn + n) * Dd + d];
    }
    for (int i = tid; i < CTX_L * Dd; i += 256) {
        int t = i / Dd, d = i - t * Dd;
        xs[i] = emb[(size_t)safe_id(ctx_ids, m * CTX_L + t) * Dd + d];
    }
    __syncthreads();

    const float4* cs4 = (const float4*)cs;
    const float4* xs4 = (const float4*)xs;
    for (int idx = tid; idx < Nn * CTX_L; idx += 256) {
        int n = idx / CTX_L, t = idx - n * CTX_L;
        float4 a = make_float4(0.f, 0.f, 0.f, 0.f);
#pragma unroll 5
        for (int j = 0; j < 75; j++) {
            float4 cv = cs4[n * 75 + j];
            float4 xv = xs4[t * 75 + j];
            a.x = fmaf(cv.x, xv.x, a.x);
            a.y = fmaf(cv.y, xv.y, a.y);
            a.z = fmaf(cv.z, xv.z, a.z);
            a.w = fmaf(cv.w, xv.w, a.w);
        }
        tok[idx] = (a.x + a.y) + (a.z + a.w);
    }
    __syncthreads();
    if (tid < CTX_L) {
        float mx = -1e30f;
        for (int n = 0; n < Nn; n++) mx = fmaxf(mx, tok[n * CTX_L + tid]);
        p[tid] = mx;
    }
    __syncthreads();
    if (tid < 32) {
        float mx = -1e30f;
        for (int t = tid; t < CTX_L; t += 32) mx = fmaxf(mx, p[t]);
        mx = warp_max(mx);
        float sum = 0.f;
        for (int t = tid; t < CTX_L; t += 32) {
            float e = expf(p[t] - mx);
            p[t] = e;
            sum += e;
        }
        sum = warp_sum(sum);
        float inv = 1.f / sum;
        for (int t = tid; t < CTX_L; t += 32) p[t] *= inv;
    }
    __syncthreads();
    for (int d = tid; d < Dd; d += 256) {
        float s = 0.f;
        for (int t = 0; t < CTX_L; t++) s = fmaf(p[t], xs[t * Dd + d], s);
        ctxv[d] = s;
    }
    __syncthreads();
    const int wid = tid >> 5, lane = tid & 31;
    for (int n = wid; n < Nn; n += 8) {
        float s = 0.f;
        for (int d = lane; d < Dd; d += 32) s = fmaf(cs[n * Dd + d], ctxv[d], s);
        s = warp_sum(s);
        if (lane == 0) g_local[m * Nn + n] = s;
    }
}

// ---------------- prep ----------------
__global__ void prep_kernel(const float* __restrict__ title,
                            const float* __restrict__ md) {
    const int w = threadIdx.x >> 5, lane = threadIdx.x & 31;
    float st2 = 0.f, smt = 0.f, sm2 = 0.f;
    for (int j = lane; j < Ff; j += 32) {
        float t = title[w * Ff + j];
        float mv = md[j];
        st2 = fmaf(t, t, st2);
        smt = fmaf(t, mv, smt);
        sm2 = fmaf(mv, mv, sm2);
    }
    st2 = warp_sum(st2);
    smt = warp_sum(smt);
    sm2 = warp_sum(sm2);
    if (lane == 0) {
        float tnv = sqrtf(st2);
        g_tn[w] = tnv;
        g_cosdt[w] = smt / (fmaxf(sqrtf(sm2), 1e-6f) * fmaxf(tnv, 1e-6f));
    }
}

// ---------------- final ----------------
__global__ void final_kernel(const float* __restrict__ title,
                             const float* __restrict__ prior,
                             const float* __restrict__ hand,
                             const float* __restrict__ w7,
                             const float* __restrict__ b7,
                             float* __restrict__ out) {
    const int m = blockIdx.x;
    const int tid = threadIdx.x;  // 256
    const int wid = tid >> 5, lane = tid & 31;
    __shared__ float nms_s, nmc_s;
    __shared__ float dst[Nn], dct[Nn], sc[Nn];

    if (wid == 0) {
        float s = 0.f;
        for (int j = lane; j < Ff; j += 32) {
            float v = g_ms[m * Ff + j];
            s = fmaf(v, v, s);
        }
        s = warp_sum(s);
        if (lane == 0) nms_s = fmaxf(sqrtf(s), 1e-6f);
    }
    if (wid == 1) {
        float s = 0.f;
        for (int j = lane; j < Ff; j += 32) {
            float v = g_mc[m * Ff + j];
            s = fmaf(v, v, s);
        }
        s = warp_sum(s);
        if (lane == 0) nmc_s = fmaxf(sqrtf(s), 1e-6f);
    }
    for (int item = wid; item < 32; item += 8) {
        int n = item & 15;
        int which = item >> 4;
        const float* a = which ? (g_mc + m * Ff) : (g_ms + m * Ff);
        float s = 0.f;
        for (int j = lane; j < Ff; j += 32) s = fmaf(a[j], title[n * Ff + j], s);
        s = warp_sum(s);
        if (lane == 0) {
            if (which) dct[n] = s;
            else dst[n] = s;
        }
    }
    __syncthreads();

    if (tid < Nn) {
        int n = tid;
        float tc = fmaxf(g_tn[n], 1e-6f);
        float cst = dst[n] / (nms_s * tc);
        float cct = dct[n] / (nmc_s * tc);
        float s = b7[0];
        s = fmaf(w7[0], hand[n], s);
        s = fmaf(w7[1], prior[n], s);
        s = fmaf(w7[2], g_local[m * Nn + n], s);
        s = fmaf(w7[3], g_attscore[n], s);
        s = fmaf(w7[4], cst, s);
        s = fmaf(w7[5], g_cosdt[n], s);
        s = fmaf(w7[6], cct, s);
        sc[n] = s;
    }
    __syncthreads();
    if (tid < Nn) {
        float x = sc[tid];
        float mu = r16_sum(x) * (1.f / 16.f);
        float dv = x - mu;
        float var = r16_sum(dv * dv) * (1.f / 15.f);
        float z = dv / sqrtf(var);
        out[m * Nn + tid] = z;
        float zmax = r16_max(z);
        float zmin = r16_min(z);
        float e = expf(z - zmax);
        float es = r16_sum(e);
        out[Mm * Nn + m * Nn + tid] = e / es;
        float u = (z + 1.f - zmin) / (zmax - zmin);
        float us = r16_sum(u);
        out[2 * Mm * Nn + m * Nn + tid] = u / us;
    }
}

// ---------------- launch ----------------
extern "C" void kernel_launch(void* const* d_in, const int* in_sizes, int n_in,
                              void* d_out, int out_size) {
    int e = -1;
    for (int i = 0; i < n_in; i++) {
        if (in_sizes[i] == VOCAB * Dd) { e = i; break; }
    }
    if (e < 0) e = 14;

    const int* mention_vec  = (const int*)d_in[e - 11];
    const int* context_vec  = (const int*)d_in[e - 10];
    const int* doc_vec      = (const int*)d_in[e - 9];
    const float* title      = (const float*)d_in[e - 8];
    const int* body_vec     = (const int*)d_in[e - 7];
    const float* prior      = (const float*)d_in[e - 5];
    const int* men2cands    = (const int*)d_in[e - 4];
    const int* contexts_ids = (const int*)d_in[e - 3];
    const float* hand       = (const float*)d_in[e - 2];
    const float* bert       = (const float*)d_in[e - 1];
    const float* emb        = (const float*)d_in[e];
    const float* Wms        = (const float*)d_in[e + 1];
    const float* bms        = (const float*)d_in[e + 2];
    const float* Wmc        = (const float*)d_in[e + 3];
    const float* bmc        = (const float*)d_in[e + 4];
    const float* w7         = (const float*)d_in[e + 5];
    const float* b7         = (const float*)d_in[e + 6];
    const float* W1         = (const float*)d_in[e + 7];
    const float* b1         = (const float*)d_in[e + 8];
    const float* W2         = (const float*)d_in[e + 9];
    const float* b2         = (const float*)d_in[e + 10];
    float* out = (float*)d_out;

    static bool s_init = false;
    static cudaStream_t s0, s1, s2;
    static cudaEvent_t evF, ev0, ev1, ev2;
    if (!s_init) {
        cudaStreamCreateWithFlags(&s0, cudaStreamNonBlocking);
        cudaStreamCreateWithFlags(&s1, cudaStreamNonBlocking);
        cudaStreamCreateWithFlags(&s2, cudaStreamNonBlocking);
        cudaEventCreateWithFlags(&evF, cudaEventDisableTiming);
        cudaEventCreateWithFlags(&ev0, cudaEventDisableTiming);
        cudaEventCreateWithFlags(&ev1, cudaEventDisableTiming);
        cudaEventCreateWithFlags(&ev2, cudaEventDisableTiming);
        s_init = true;
    }

    cudaFuncSetAttribute(attn_kernel, cudaFuncAttributeMaxDynamicSharedMemorySize, 100000);
    cudaFuncSetAttribute(localctx_kernel, cudaFuncAttributeMaxDynamicSharedMemorySize, 84000);
    cudaFuncSetAttribute(conv_mma2_kernel, cudaFuncAttributeMaxDynamicSharedMemorySize, SMEM_CONV);

    cudaEventRecord(evF, 0);
    cudaStreamWaitEvent(s0, evF, 0);
    cudaStreamWaitEvent(s1, evF, 0);
    cudaStreamWaitEvent(s2, evF, 0);

    // s0: weight prep -> convs
    wprep_kernel<<<(Ff * 5 * KDP + 2 * Dd * Ff + 255) / 256, 256, 0, s0>>>(Wms, Wmc);
    conv_ms_kernel<<<Mm, 192, 0, s0>>>(mention_vec, emb, bms);
    conv_mma2_kernel<<<dim3(Mm / 2, Ff / 128), 256, SMEM_CONV, s0>>>(context_vec, emb, bmc);
    cudaEventRecord(ev0, s0);

    // s1: cross attention (chunked) + MLP score
    attn_kernel<<<dim3(Nn, NH, 6), 256, 100000, s1>>>(doc_vec, body_vec, emb);
    attmlp_kernel<<<Nn, 320, 0, s1>>>(W1, b1, W2, b2);
    cudaEventRecord(ev1, s1);

    // s2: local context ranker + title prep
    localctx_kernel<<<Mm, 256, 84000, s2>>>(men2cands, contexts_ids, emb);
    prep_kernel<<<1, 512, 0, s2>>>(title, bert);
    cudaEventRecord(ev2, s2);

    cudaStreamWaitEvent(0, ev0, 0);
    cudaStreamWaitEvent(0, ev1, 0);
    cudaStreamWaitEvent(0, ev2, 0);

    final_kernel<<<Mm, 256>>>(title, prior, hand, w7, b7, out);
}

// round 13
// speedup vs baseline: 2.2001x; 1.2472x over previous
#include <cuda_runtime.h>
#include <cuda_bf16.h>
#include <math.h>

#define Mm 64
#define Nn 16
#define Dd 300
#define Ff 768
#define VOCAB 100000
#define SURF_L 4
#define CTX_L 50
#define DOC_L 100
#define BODY_L 200
#define HD 60
#define NH 5

#define KD 304               // padded d per tap
#define KDP (KD / 2)         // u32 pairs per tap row = 152
#define ESTR 201             // E row stride (odd -> conflict-free column walks)

typedef unsigned long long u64;
typedef unsigned int u32;

// ---------------- scratch (__device__ globals, no allocation) ----------------
__device__ float g_Wt_ms[2 * Dd * Ff];
__device__ u32 g_WbH[Ff * 5 * KDP + 32];   // +32 pad: kh1 stage reads 8 uint4 past end
__device__ u32 g_WbL[Ff * 5 * KDP + 32];
__device__ float g_ms[Mm * Ff];
__device__ float g_mc[Mm * Ff];
__device__ float g_comb[Nn * 600];
__device__ float g_attscore[Nn];
__device__ float g_local[Mm * Nn];
__device__ float g_tn[Nn];
__device__ float g_cosdt[Nn];

__device__ __forceinline__ int safe_id(const int* p, int i) {
    int v = p[i];
    return v < 0 ? 0 : (v >= VOCAB ? VOCAB - 1 : v);
}
__device__ __forceinline__ u32 smem_to_u32(const void* p) {
    u32 a;
    asm("{ .reg .u64 t; cvta.to.shared.u64 t, %1; cvt.u32.u64 %0, t; }" : "=r"(a) : "l"(p));
    return a;
}
__device__ __forceinline__ void ldsm_x4(u32 addr, u32& r0, u32& r1, u32& r2, u32& r3) {
    asm volatile("ldmatrix.sync.aligned.m8n8.x4.shared.b16 {%0,%1,%2,%3}, [%4];"
                 : "=r"(r0), "=r"(r1), "=r"(r2), "=r"(r3) : "r"(addr));
}
__device__ __forceinline__ void mma_bf16(float* c, u32 a0, u32 a1, u32 a2, u32 a3,
                                         u32 b0, u32 b1) {
    asm volatile(
        "mma.sync.aligned.m16n8k16.row.col.f32.bf16.bf16.f32 "
        "{%0,%1,%2,%3}, {%4,%5,%6,%7}, {%8,%9}, {%0,%1,%2,%3};"
        : "+f"(c[0]), "+f"(c[1]), "+f"(c[2]), "+f"(c[3])
        : "r"(a0), "r"(a1), "r"(a2), "r"(a3), "r"(b0), "r"(b1));
}
__device__ __forceinline__ void cp_async16(u32 dst, const void* src) {
    asm volatile("cp.async.cg.shared.global [%0], [%1], 16;" :: "r"(dst), "l"(src));
}
__device__ __forceinline__ void split_pair(float a, float b, u32& hi, u32& lo) {
    __nv_bfloat16 ha = __float2bfloat16(a);
    __nv_bfloat16 hb = __float2bfloat16(b);
    __nv_bfloat16 la = __float2bfloat16(a - __bfloat162float(ha));
    __nv_bfloat16 lb = __float2bfloat16(b - __bfloat162float(hb));
    hi = ((u32)__bfloat16_as_ushort(hb) << 16) | (u32)__bfloat16_as_ushort(ha);
    lo = ((u32)__bfloat16_as_ushort(lb) << 16) | (u32)__bfloat16_as_ushort(la);
}

__device__ __forceinline__ float warp_sum(float v) {
#pragma unroll
    for (int o = 16; o; o >>= 1) v += __shfl_xor_sync(0xFFFFFFFFu, v, o);
    return v;
}
__device__ __forceinline__ float warp_max(float v) {
#pragma unroll
    for (int o = 16; o; o >>= 1) v = fmaxf(v, __shfl_xor_sync(0xFFFFFFFFu, v, o));
    return v;
}
__device__ __forceinline__ float r16_sum(float v) {
#pragma unroll
    for (int o = 8; o; o >>= 1) v += __shfl_xor_sync(0xFFFFu, v, o, 16);
    return v;
}
__device__ __forceinline__ float r16_max(float v) {
#pragma unroll
    for (int o = 8; o; o >>= 1) v = fmaxf(v, __shfl_xor_sync(0xFFFFu, v, o, 16));
    return v;
}
__device__ __forceinline__ float r16_min(float v) {
#pragma unroll
    for (int o = 8; o; o >>= 1) v = fminf(v, __shfl_xor_sync(0xFFFFu, v, o, 16));
    return v;
}

// ---------------- weight prep ----------------
__global__ void wprep_kernel(const float* __restrict__ Wms,
                             const float* __restrict__ Wmc) {
    int idx = blockIdx.x * blockDim.x + threadIdx.x;
    const int nW = Ff * 5 * KDP;
    if (idx < nW) {
        int f = idx / (5 * KDP);
        int r = idx - f * (5 * KDP);
        int tap = r / KDP;
        int dp = r - tap * KDP;
        int d = 2 * dp;
        float a = (d < Dd) ? Wmc[(size_t)f * Dd * 5 + d * 5 + tap] : 0.f;
        float b = (d + 1 < Dd) ? Wmc[(size_t)f * Dd * 5 + (d + 1) * 5 + tap] : 0.f;
        u32 hi, lo;
        split_pair(a, b, hi, lo);
        g_WbH[idx] = hi;
        g_WbL[idx] = lo;
    } else {
        int i = idx - nW;
        if (i < 2 * Dd * Ff) {
            int f = i % Ff;
            int rest = i / Ff;
            int d = rest % Dd;
            int k = rest / Dd;
            g_Wt_ms[i] = Wms[(size_t)f * Dd * 2 + d * 2 + k];
        }
    }
}

// ---------------- surface conv ----------------
__launch_bounds__(192)
__global__ void conv_ms_kernel(const int* __restrict__ ids,
                               const float* __restrict__ emb,
                               const float* __restrict__ bias) {
    const int m = blockIdx.x;
    const int tid = threadIdx.x;
    __shared__ float Xs[SURF_L * Dd];
    for (int i = tid; i < SURF_L * Dd; i += 192) {
        int l = i / Dd, d = i - l * Dd;
        Xs[i] = emb[(size_t)safe_id(ids, m * SURF_L + l) * Dd + d];
    }
    __syncthreads();
    float4 acc[3];
#pragma unroll
    for (int t = 0; t < 3; t++) acc[t] = make_float4(0.f, 0.f, 0.f, 0.f);
#pragma unroll
    for (int k = 0; k < 2; k++) {
        const float4* __restrict__ wp = (const float4*)(g_Wt_ms + (size_t)k * Dd * Ff) + tid;
        const float* __restrict__ xk = Xs + k * Dd;
        for (int d = 0; d < Dd; d++) {
            float4 w = wp[(size_t)d * (Ff / 4)];
#pragma unroll
            for (int t = 0; t < 3; t++) {
                float xv = xk[t * Dd + d];
                acc[t].x = fmaf(xv, w.x, acc[t].x);
                acc[t].y = fmaf(xv, w.y, acc[t].y);
                acc[t].z = fmaf(xv, w.z, acc[t].z);
                acc[t].w = fmaf(xv, w.w, acc[t].w);
            }
        }
    }
    float4 b4 = ((const float4*)bias)[tid];
    float4 s = make_float4(0.f, 0.f, 0.f, 0.f);
#pragma unroll
    for (int t = 0; t < 3; t++) {
        s.x += fmaxf(acc[t].x + b4.x, 0.f);
        s.y += fmaxf(acc[t].y + b4.y, 0.f);
        s.z += fmaxf(acc[t].z + b4.z, 0.f);
        s.w += fmaxf(acc[t].w + b4.w, 0.f);
    }
    s.x *= (1.f / 3.f); s.y *= (1.f / 3.f); s.z *= (1.f / 3.f); s.w *= (1.f / 3.f);
    ((float4*)(g_ms + (size_t)m * Ff))[tid] = s;
}

// ---------------- context conv: mma.sync + cp.async double-buffered W (R12) ----------------
#define XHALF 31616
#define XMEN (2 * XHALF)
#define WS0 126464
#define WSLAB 40960
#define WS1 (WS0 + WSLAB)
#define SMEM_CONV (WS1 + WSLAB)  // 208384

__global__ void __launch_bounds__(256, 1)
conv_mma2_kernel(const int* __restrict__ ids,
                 const float* __restrict__ emb,
                 const float* __restrict__ bias) {
    extern __shared__ char smem[];
    const int tid = threadIdx.x;
    const int lane = tid & 31;
    const int w = tid >> 5;
    const int mi = w >> 2, nq = w & 3;
    const int mp = blockIdx.x;
    const int f0 = blockIdx.y * 128;

    const u32 sb = smem_to_u32(smem);

    auto stage_issue = [&](int s) {
        int half = s / 10, rem = s - half * 10;
        int tap = rem >> 1, kh = rem & 1;
        const u32* src = half ? g_WbL : g_WbH;
        u32 dst = sb + (u32)((s & 1) ? WS1 : WS0);
        for (int i = tid; i < 128 * 20; i += 256) {
            int row = i / 20, c = i - row * 20;
            const void* g = src + (size_t)(((f0 + row) * 5 + tap) * 38 + kh * 20 + c) * 4;
            cp_async16(dst + (u32)i * 16, g);
        }
    };

    for (int i = tid; i < 2 * 52 * KDP; i += 256) {
        int m2 = i / (52 * KDP);
        int rem = i - m2 * (52 * KDP);
        int row = rem / KDP;
        int dp = rem - row * KDP;
        int d = 2 * dp;
        float a = 0.f, b = 0.f;
        if (row < CTX_L) {
            const float* er = emb + (size_t)safe_id(ids, (mp * 2 + m2) * CTX_L + row) * Dd;
            if (d < Dd) a = er[d];
            if (d + 1 < Dd) b = er[d + 1];
        }
        u32 hi, lo;
        split_pair(a, b, hi, lo);
        ((u32*)(smem + m2 * XMEN))[row * KDP + dp] = hi;
        ((u32*)(smem + m2 * XMEN + XHALF))[row * KDP + dp] = lo;
    }

    const u32 xbase = sb + (u32)(mi * XMEN);
    const int a_r = lane & 15;
    const int a_k = (lane >> 4) << 3;
    const int b_n = ((lane >> 4) << 3) + (lane & 7);
    const int b_k = ((lane >> 3) & 1) << 3;

    float C[3][4][4];
#pragma unroll
    for (int mt = 0; mt < 3; mt++)
#pragma unroll
        for (int nt = 0; nt < 4; nt++)
#pragma unroll
            for (int j = 0; j < 4; j++) C[mt][nt][j] = 0.f;

    stage_issue(0);
    asm volatile("cp.async.commit_group;" ::: "memory");
    __syncthreads();

    for (int s = 0; s < 20; s++) {
        if (s + 1 < 20) stage_issue(s + 1);
        asm volatile("cp.async.commit_group;" ::: "memory");
        asm volatile("cp.async.wait_group 1;" ::: "memory");
        __syncthreads();

        const int half = s / 10, rem = s - half * 10;
        const int tap = rem >> 1, kh = rem & 1;
        const u32 buf = sb + (u32)((s & 1) ? WS1 : WS0);
        const int nks = kh ? 9 : 10;
        const int xk0 = kh ? 160 : 0;
        for (int ks = 0; ks < nks; ks++) {
            const int k0 = ks * 16;
            u32 Bf[4][2];
#pragma unroll
            for (int p = 0; p < 2; p++) {
                u32 addr = buf + (u32)(((nq * 32 + p * 16 + b_n) * 160 + k0 + b_k) * 2);
                ldsm_x4(addr, Bf[2 * p][0], Bf[2 * p][1], Bf[2 * p + 1][0], Bf[2 * p + 1][1]);
            }
#pragma unroll
            for (int mt = 0; mt < 3; mt++) {
                u32 aoff = (u32)(((mt * 16 + tap + a_r) * KD + xk0 + k0 + a_k) * 2);
                u32 A0, A1, A2, A3;
                ldsm_x4(xbase + aoff, A0, A1, A2, A3);
#pragma unroll
                for (int nt = 0; nt < 4; nt++)
                    mma_bf16(C[mt][nt], A0, A1, A2, A3, Bf[nt][0], Bf[nt][1]);
                if (half == 0) {
                    ldsm_x4(xbase + XHALF + aoff, A0, A1, A2, A3);
#pragma unroll
                    for (int nt = 0; nt < 4; nt++)
                        mma_bf16(C[mt][nt], A0, A1, A2, A3, Bf[nt][0], Bf[nt][1]);
                }
            }
        }
        __syncthreads();
    }

    float* stg = (float*)(smem + WS0);
#pragma unroll
    for (int mt = 0; mt < 3; mt++)
#pragma unroll
        for (int nt = 0; nt < 4; nt++) {
            int row = mt * 16 + (lane >> 2);
            int col = nq * 32 + nt * 8 + (lane & 3) * 2;
            float* base = stg + mi * 6144 + row * 128 + col;
            base[0] = C[mt][nt][0];
            base[1] = C[mt][nt][1];
            base[8 * 128] = C[mt][nt][2];
            base[8 * 128 + 1] = C[mt][nt][3];
        }
    __syncthreads();
    {
        int m2 = tid >> 7, f = tid & 127;
        float b = bias[f0 + f];
        float s = 0.f;
        for (int t = 0; t < 46; t++) s += fmaxf(stg[m2 * 6144 + t * 128 + f] + b, 0.f);
        g_mc[(size_t)(mp * 2 + m2) * Ff + f0 + f] = s * (1.0f / 46.0f);
    }
}

// ---------------- cross attention v3: one block per (n,h), shared E matrix ----------------
// D[q][k] = doc_q . body_k * scale; E = exp(D - globalM);
// dir0 out[q][j] = (1/rowsum_q) sum_k E[q][k] body[k][j], max over q
// dir1 out[b][j] = (1/colsum_b) sum_d E[d][b] doc[d][j], max over b
// smem floats: qs[6000] ks[12000] E[100*201] rs[100] cs[200] red[512] rowm[100]
#define AT_QS 0
#define AT_KS 6000
#define AT_E  18000
#define AT_RS 38100
#define AT_CS 38200
#define AT_RED 38400
#define AT_RM 38912
#define SMEM_ATTN ((38912 + 128) * 4)   // 156160 B

__global__ void __launch_bounds__(256, 1)
attn_kernel(const int* __restrict__ doc_ids,
            const int* __restrict__ body_ids,
            const float* __restrict__ emb) {
    const int n = blockIdx.x, h = blockIdx.y;
    extern __shared__ float sh[];
    float* qs = sh + AT_QS;
    float* ks = sh + AT_KS;
    float* E = sh + AT_E;
    float* rs = sh + AT_RS;
    float* cs = sh + AT_CS;
    float* red = sh + AT_RED;    // [8][64]
    float* rowm = sh + AT_RM;
    __shared__ float Msh;

    const int tid = threadIdx.x, wid = tid >> 5, lane = tid & 31;
    const int* bids = body_ids + n * BODY_L;

    for (int i = tid; i < DOC_L * HD; i += 256) {
        int l = i / HD, j = i - l * HD;
        qs[i] = emb[(size_t)safe_id(doc_ids, l) * Dd + h * HD + j];
    }
    for (int i = tid; i < BODY_L * HD; i += 256) {
        int l = i / HD, j = i - l * HD;
        ks[i] = emb[(size_t)safe_id(bids, l) * Dd + h * HD + j];
    }
    __syncthreads();

    // ---- D phase: thread = (q, k-half); q row held in registers
    const float scale = rsqrtf((float)HD);
    {
        int q = tid >> 1, half = tid & 1;
        if (q < DOC_L) {
            float4 qv[15];
            const float4* q4 = (const float4*)(qs + q * HD);
#pragma unroll
            for (int j = 0; j < 15; j++) qv[j] = q4[j];
            float* Erow = E + q * ESTR + half * 100;
            for (int i = 0; i < 100; i++) {
                const float4* k4 = (const float4*)(ks + (half * 100 + i) * HD);
                float a0 = 0.f, a1 = 0.f, a2 = 0.f, a3 = 0.f;
#pragma unroll
                for (int j = 0; j < 15; j++) {
                    float4 kv = k4[j];
                    a0 = fmaf(qv[j].x, kv.x, a0);
                    a1 = fmaf(qv[j].y, kv.y, a1);
                    a2 = fmaf(qv[j].z, kv.z, a2);
                    a3 = fmaf(qv[j].w, kv.w, a3);
                }
                Erow[i] = ((a0 + a1) + (a2 + a3)) * scale;
            }
        }
    }
    __syncthreads();

    // ---- global max
    for (int q = wid; q < DOC_L; q += 8) {
        float mx = -1e30f;
        for (int k = lane; k < BODY_L; k += 32) mx = fmaxf(mx, E[q * ESTR + k]);
        mx = warp_max(mx);
        if (lane == 0) rowm[q] = mx;
    }
    __syncthreads();
    if (wid == 0) {
        float mx = -1e30f;
        for (int i = lane; i < DOC_L; i += 32) mx = fmaxf(mx, rowm[i]);
        mx = warp_max(mx);
        if (lane == 0) Msh = mx;
    }
    __syncthreads();
    const float M = Msh;

    // ---- E = exp(D - M), row sums
    for (int q = wid; q < DOC_L; q += 8) {
        float s = 0.f;
        for (int k = lane; k < BODY_L; k += 32) {
            float e = expf(E[q * ESTR + k] - M);
            E[q * ESTR + k] = e;
            s += e;
        }
        s = warp_sum(s);
        if (lane == 0) rs[q] = s;
    }
    __syncthreads();

    // ---- column sums (stride 201 -> conflict-free)
    for (int c = wid; c < BODY_L; c += 8) {
        float s = 0.f;
        for (int d = lane; d < DOC_L; d += 32) s += E[d * ESTR + c];
        s = warp_sum(s);
        if (lane == 0) cs[c] = s;
    }
    __syncthreads();

    // ---- PV dir0: rows q (100, groups of 4), V = body
    {
        float2 mx = make_float2(-1e30f, -1e30f);
        if (lane < 30) {
            const float2* V = (const float2*)ks;
            for (int g = wid; g < 25; g += 8) {
                int q0 = g * 4;
                float2 a0 = make_float2(0.f, 0.f), a1 = a0, a2 = a0, a3 = a0;
                for (int k = 0; k < BODY_L; k++) {
                    float2 v = V[k * 30 + lane];
                    float e0 = E[(q0 + 0) * ESTR + k];
                    float e1 = E[(q0 + 1) * ESTR + k];
                    float e2 = E[(q0 + 2) * ESTR + k];
                    float e3 = E[(q0 + 3) * ESTR + k];
                    a0.x = fmaf(e0, v.x, a0.x); a0.y = fmaf(e0, v.y, a0.y);
                    a1.x = fmaf(e1, v.x, a1.x); a1.y = fmaf(e1, v.y, a1.y);
                    a2.x = fmaf(e2, v.x, a2.x); a2.y = fmaf(e2, v.y, a2.y);
                    a3.x = fmaf(e3, v.x, a3.x); a3.y = fmaf(e3, v.y, a3.y);
                }
                float i0 = 1.f / rs[q0], i1 = 1.f / rs[q0 + 1];
                float i2 = 1.f / rs[q0 + 2], i3 = 1.f / rs[q0 + 3];
                mx.x = fmaxf(mx.x, fmaxf(fmaxf(a0.x * i0, a1.x * i1), fmaxf(a2.x * i2, a3.x * i3)));
                mx.y = fmaxf(mx.y, fmaxf(fmaxf(a0.y * i0, a1.y * i1), fmaxf(a2.y * i2, a3.y * i3)));
            }
            red[wid * 64 + 2 * lane] = mx.x;
            red[wid * 64 + 2 * lane + 1] = mx.y;
        }
        __syncthreads();
        if (tid < 60) {
            float m = -1e30f;
#pragma unroll
            for (int g = 0; g < 8; g++) m = fmaxf(m, red[g * 64 + tid]);
            g_comb[n * 600 + h * HD + tid] = m;
        }
        __syncthreads();
    }

    // ---- PV dir1: rows b (200, groups of 4), weights = E column b, V = doc
    {
        float2 mx = make_float2(-1e30f, -1e30f);
        if (lane < 30) {
            const float2* V = (const float2*)qs;
            for (int g = wid; g < 50; g += 8) {
                int b0 = g * 4;
                float2 a0 = make_float2(0.f, 0.f), a1 = a0, a2 = a0, a3 = a0;
                for (int d = 0; d < DOC_L; d++) {
                    float2 v = V[d * 30 + lane];
                    const float* Er = E + d * ESTR + b0;
                    float e0 = Er[0], e1 = Er[1], e2 = Er[2], e3 = Er[3];
                    a0.x = fmaf(e0, v.x, a0.x); a0.y = fmaf(e0, v.y, a0.y);
                    a1.x = fmaf(e1, v.x, a1.x); a1.y = fmaf(e1, v.y, a1.y);
                    a2.x = fmaf(e2, v.x, a2.x); a2.y = fmaf(e2, v.y, a2.y);
                    a3.x = fmaf(e3, v.x, a3.x); a3.y = fmaf(e3, v.y, a3.y);
                }
                float i0 = 1.f / cs[b0], i1 = 1.f / cs[b0 + 1];
                float i2 = 1.f / cs[b0 + 2], i3 = 1.f / cs[b0 + 3];
                mx.x = fmaxf(mx.x, fmaxf(fmaxf(a0.x * i0, a1.x * i1), fmaxf(a2.x * i2, a3.x * i3)));
                mx.y = fmaxf(mx.y, fmaxf(fmaxf(a0.y * i0, a1.y * i1), fmaxf(a2.y * i2, a3.y * i3)));
            }
            red[wid * 64 + 2 * lane] = mx.x;
            red[wid * 64 + 2 * lane + 1] = mx.y;
        }
        __syncthreads();
        if (tid < 60) {
            float m = -1e30f;
#pragma unroll
            for (int g = 0; g < 8; g++) m = fmaxf(m, red[g * 64 + tid]);
            g_comb[n * 600 + 300 + h * HD + tid] = m;
        }
    }
}

// ---------------- attention MLP ----------------
__global__ void attmlp_kernel(const float* __restrict__ W1,
                              const float* __restrict__ b1,
                              const float* __restrict__ W2,
                              const float* __restrict__ b2) {
    const int n = blockIdx.x;
    __shared__ float cb[600];
    __shared__ float partial[10];
    const int tid = threadIdx.x;  // 320
    for (int i = tid; i < 600; i += 320) cb[i] = g_comb[n * 600 + i];
    __syncthreads();
    float v = 0.f;
    if (tid < 300) {
        float a0 = b1[tid], a1 = 0.f, a2 = 0.f, a3 = 0.f;
        for (int i = 0; i < 600; i += 4) {
            a0 = fmaf(cb[i], W1[i * 300 + tid], a0);
            a1 = fmaf(cb[i + 1], W1[(i + 1) * 300 + tid], a1);
            a2 = fmaf(cb[i + 2], W1[(i + 2) * 300 + tid], a2);
            a3 = fmaf(cb[i + 3], W1[(i + 3) * 300 + tid], a3);
        }
        float a = (a0 + a1) + (a2 + a3);
        a = fmaxf(a, 0.f);
        v = a * W2[tid];
    }
    v = warp_sum(v);
    if ((tid & 31) == 0) partial[tid >> 5] = v;
    __syncthreads();
    if (tid == 0) {
        float s = 0.f;
        for (int w = 0; w < 10; w++) s += partial[w];
        s += b2[0];
        g_attscore[n] = 1.f / (1.f + expf(-s));
    }
}

// ---------------- LocalCtxAttRanker ----------------
__global__ void localctx_kernel(const int* __restrict__ cand_ids,
                                const int* __restrict__ ctx_ids,
                                const float* __restrict__ emb) {
    const int m = blockIdx.x;
    extern __shared__ float sh[];
    float* cs = sh;
    float* xs = cs + Nn * Dd;
    float* tok = xs + CTX_L * Dd;
    float* p = tok + Nn * CTX_L;
    float* ctxv = p + CTX_L;
    const int tid = threadIdx.x;  // 256

    for (int i = tid; i < Nn * Dd; i += 256) {
        int n = i / Dd, d = i - n * Dd;
        cs[i] = emb[(size_t)safe_id(cand_ids, m * Nn + n) * Dd + d];
    }
    for (int i = tid; i < CTX_L * Dd; i += 256) {
        int t = i / Dd, d = i - t * Dd;
        xs[i] = emb[(size_t)safe_id(ctx_ids, m * CTX_L + t) * Dd + d];
    }
    __syncthreads();

    const float4* cs4 = (const float4*)cs;
    const float4* xs4 = (const float4*)xs;
    for (int idx = tid; idx < Nn * CTX_L; idx += 256) {
        int n = idx / CTX_L, t = idx - n * CTX_L;
        float4 a = make_float4(0.f, 0.f, 0.f, 0.f);
#pragma unroll 5
        for (int j = 0; j < 75; j++) {
            float4 cv = cs4[n * 75 + j];
            float4 xv = xs4[t * 75 + j];
            a.x = fmaf(cv.x, xv.x, a.x);
            a.y = fmaf(cv.y, xv.y, a.y);
            a.z = fmaf(cv.z, xv.z, a.z);
            a.w = fmaf(cv.w, xv.w, a.w);
        }
        tok[idx] = (a.x + a.y) + (a.z + a.w);
    }
    __syncthreads();
    if (tid < CTX_L) {
        float mx = -1e30f;
        for (int n = 0; n < Nn; n++) mx = fmaxf(mx, tok[n * CTX_L + tid]);
        p[tid] = mx;
    }
    __syncthreads();
    if (tid < 32) {
        float mx = -1e30f;
        for (int t = tid; t < CTX_L; t += 32) mx = fmaxf(mx, p[t]);
        mx = warp_max(mx);
        float sum = 0.f;
        for (int t = tid; t < CTX_L; t += 32) {
            float e = expf(p[t] - mx);
            p[t] = e;
            sum += e;
        }
        sum = warp_sum(sum);
        float inv = 1.f / sum;
        for (int t = tid; t < CTX_L; t += 32) p[t] *= inv;
    }
    __syncthreads();
    for (int d = tid; d < Dd; d += 256) {
        float s = 0.f;
        for (int t = 0; t < CTX_L; t++) s = fmaf(p[t], xs[t * Dd + d], s);
        ctxv[d] = s;
    }
    __syncthreads();
    const int wid = tid >> 5, lane = tid & 31;
    for (int n = wid; n < Nn; n += 8) {
        float s = 0.f;
        for (int d = lane; d < Dd; d += 32) s = fmaf(cs[n * Dd + d], ctxv[d], s);
        s = warp_sum(s);
        if (lane == 0) g_local[m * Nn + n] = s;
    }
}

// ---------------- prep ----------------
__global__ void prep_kernel(const float* __restrict__ title,
                            const float* __restrict__ md) {
    const int w = threadIdx.x >> 5, lane = threadIdx.x & 31;
    float st2 = 0.f, smt = 0.f, sm2 = 0.f;
    for (int j = lane; j < Ff; j += 32) {
        float t = title[w * Ff + j];
        float mv = md[j];
        st2 = fmaf(t, t, st2);
        smt = fmaf(t, mv, smt);
        sm2 = fmaf(mv, mv, sm2);
    }
    st2 = warp_sum(st2);
    smt = warp_sum(smt);
    sm2 = warp_sum(sm2);
    if (lane == 0) {
        float tnv = sqrtf(st2);
        g_tn[w] = tnv;
        g_cosdt[w] = smt / (fmaxf(sqrtf(sm2), 1e-6f) * fmaxf(tnv, 1e-6f));
    }
}

// ---------------- final ----------------
__global__ void final_kernel(const float* __restrict__ title,
                             const float* __restrict__ prior,
                             const float* __restrict__ hand,
                             const float* __restrict__ w7,
                             const float* __restrict__ b7,
                             float* __restrict__ out) {
    const int m = blockIdx.x;
    const int tid = threadIdx.x;  // 256
    const int wid = tid >> 5, lane = tid & 31;
    __shared__ float nms_s, nmc_s;
    __shared__ float dst[Nn], dct[Nn], sc[Nn];

    if (wid == 0) {
        float s = 0.f;
        for (int j = lane; j < Ff; j += 32) {
            float v = g_ms[m * Ff + j];
            s = fmaf(v, v, s);
        }
        s = warp_sum(s);
        if (lane == 0) nms_s = fmaxf(sqrtf(s), 1e-6f);
    }
    if (wid == 1) {
        float s = 0.f;
        for (int j = lane; j < Ff; j += 32) {
            float v = g_mc[m * Ff + j];
            s = fmaf(v, v, s);
        }
        s = warp_sum(s);
        if (lane == 0) nmc_s = fmaxf(sqrtf(s), 1e-6f);
    }
    for (int item = wid; item < 32; item += 8) {
        int n = item & 15;
        int which = item >> 4;
        const float* a = which ? (g_mc + m * Ff) : (g_ms + m * Ff);
        float s = 0.f;
        for (int j = lane; j < Ff; j += 32) s = fmaf(a[j], title[n * Ff + j], s);
        s = warp_sum(s);
        if (lane == 0) {
            if (which) dct[n] = s;
            else dst[n] = s;
        }
    }
    __syncthreads();

    if (tid < Nn) {
        int n = tid;
        float tc = fmaxf(g_tn[n], 1e-6f);
        float cst = dst[n] / (nms_s * tc);
        float cct = dct[n] / (nmc_s * tc);
        float s = b7[0];
        s = fmaf(w7[0], hand[n], s);
        s = fmaf(w7[1], prior[n], s);
        s = fmaf(w7[2], g_local[m * Nn + n], s);
        s = fmaf(w7[3], g_attscore[n], s);
        s = fmaf(w7[4], cst, s);
        s = fmaf(w7[5], g_cosdt[n], s);
        s = fmaf(w7[6], cct, s);
        sc[n] = s;
    }
    __syncthreads();
    if (tid < Nn) {
        float x = sc[tid];
        float mu = r16_sum(x) * (1.f / 16.f);
        float dv = x - mu;
        float var = r16_sum(dv * dv) * (1.f / 15.f);
        float z = dv / sqrtf(var);
        out[m * Nn + tid] = z;
        float zmax = r16_max(z);
        float zmin = r16_min(z);
        float e = expf(z - zmax);
        float es = r16_sum(e);
        out[Mm * Nn + m * Nn + tid] = e / es;
        float u = (z + 1.f - zmin) / (zmax - zmin);
        float us = r16_sum(u);
        out[2 * Mm * Nn + m * Nn + tid] = u / us;
    }
}

// ---------------- launch ----------------
extern "C" void kernel_launch(void* const* d_in, const int* in_sizes, int n_in,
                              void* d_out, int out_size) {
    int e = -1;
    for (int i = 0; i < n_in; i++) {
        if (in_sizes[i] == VOCAB * Dd) { e = i; break; }
    }
    if (e < 0) e = 14;

    const int* mention_vec  = (const int*)d_in[e - 11];
    const int* context_vec  = (const int*)d_in[e - 10];
    const int* doc_vec      = (const int*)d_in[e - 9];
    const float* title      = (const float*)d_in[e - 8];
    const int* body_vec     = (const int*)d_in[e - 7];
    const float* prior      = (const float*)d_in[e - 5];
    const int* men2cands    = (const int*)d_in[e - 4];
    const int* contexts_ids = (const int*)d_in[e - 3];
    const float* hand       = (const float*)d_in[e - 2];
    const float* bert       = (const float*)d_in[e - 1];
    const float* emb        = (const float*)d_in[e];
    const float* Wms        = (const float*)d_in[e + 1];
    const float* bms        = (const float*)d_in[e + 2];
    const float* Wmc        = (const float*)d_in[e + 3];
    const float* bmc        = (const float*)d_in[e + 4];
    const float* w7         = (const float*)d_in[e + 5];
    const float* b7         = (const float*)d_in[e + 6];
    const float* W1         = (const float*)d_in[e + 7];
    const float* b1         = (const float*)d_in[e + 8];
    const float* W2         = (const float*)d_in[e + 9];
    const float* b2         = (const float*)d_in[e + 10];
    float* out = (float*)d_out;

    static bool s_init = false;
    static cudaStream_t s0, s1, s2;
    static cudaEvent_t evF, ev0, ev1, ev2;
    if (!s_init) {
        cudaStreamCreateWithFlags(&s0, cudaStreamNonBlocking);
        cudaStreamCreateWithFlags(&s1, cudaStreamNonBlocking);
        cudaStreamCreateWithFlags(&s2, cudaStreamNonBlocking);
        cudaEventCreateWithFlags(&evF, cudaEventDisableTiming);
        cudaEventCreateWithFlags(&ev0, cudaEventDisableTiming);
        cudaEventCreateWithFlags(&ev1, cudaEventDisableTiming);
        cudaEventCreateWithFlags(&ev2, cudaEventDisableTiming);
        s_init = true;
    }

    cudaFuncSetAttribute(attn_kernel, cudaFuncAttributeMaxDynamicSharedMemorySize, SMEM_ATTN);
    cudaFuncSetAttribute(localctx_kernel, cudaFuncAttributeMaxDynamicSharedMemorySize, 84000);
    cudaFuncSetAttribute(conv_mma2_kernel, cudaFuncAttributeMaxDynamicSharedMemorySize, SMEM_CONV);

    cudaEventRecord(evF, 0);
    cudaStreamWaitEvent(s0, evF, 0);
    cudaStreamWaitEvent(s1, evF, 0);
    cudaStreamWaitEvent(s2, evF, 0);

    // s0: weight prep -> convs
    wprep_kernel<<<(Ff * 5 * KDP + 2 * Dd * Ff + 255) / 256, 256, 0, s0>>>(Wms, Wmc);
    conv_ms_kernel<<<Mm, 192, 0, s0>>>(mention_vec, emb, bms);
    conv_mma2_kernel<<<dim3(Mm / 2, Ff / 128), 256, SMEM_CONV, s0>>>(context_vec, emb, bmc);
    cudaEventRecord(ev0, s0);

    // s1: cross attention (shared-E, both dirs) + MLP score
    attn_kernel<<<dim3(Nn, NH), 256, SMEM_ATTN, s1>>>(doc_vec, body_vec, emb);
    attmlp_kernel<<<Nn, 320, 0, s1>>>(W1, b1, W2, b2);
    cudaEventRecord(ev1, s1);

    // s2: local context ranker + title prep
    localctx_kernel<<<Mm, 256, 84000, s2>>>(men2cands, contexts_ids, emb);
    prep_kernel<<<1, 512, 0, s2>>>(title, bert);
    cudaEventRecord(ev2, s2);

    cudaStreamWaitEvent(0, ev0, 0);
    cudaStreamWaitEvent(0, ev1, 0);
    cudaStreamWaitEvent(0, ev2, 0);

    final_kernel<<<Mm, 256>>>(title, prior, hand, w7, b7, out);
}

// round 15
// speedup vs baseline: 2.2007x; 1.0003x over previous
#include <cuda_runtime.h>
#include <cuda_bf16.h>
#include <math.h>

#define Mm 64
#define Nn 16
#define Dd 300
#define Ff 768
#define VOCAB 100000
#define SURF_L 4
#define CTX_L 50
#define DOC_L 100
#define BODY_L 200
#define HD 60
#define NH 5

#define KD 304               // padded d per tap
#define KDP (KD / 2)         // u32 pairs per tap row = 152

typedef unsigned long long u64;
typedef unsigned int u32;

// ---------------- scratch (__device__ globals, no allocation) ----------------
__device__ float g_Wt_ms[2 * Dd * Ff];
__device__ u32 g_WbH[Ff * 5 * KDP + 32];
__device__ u32 g_WbL[Ff * 5 * KDP + 32];
__device__ float g_ms[Mm * Ff];
__device__ float g_mc[Mm * Ff];
__device__ float g_comb[Nn * 600];
__device__ float g_O0[Nn * NH * 2 * 100 * 60];   // dir0 partial PV sums
__device__ float g_rsp[Nn * NH * 2 * 100];       // dir0 partial row sums
__device__ float g_p1[Nn * NH * 2 * 64];         // dir1 partial maxes
__device__ float g_attscore[Nn];
__device__ float g_local[Mm * Nn];
__device__ float g_tn[Nn];
__device__ float g_cosdt[Nn];

__device__ __forceinline__ int safe_id(const int* p, int i) {
    int v = p[i];
    return v < 0 ? 0 : (v >= VOCAB ? VOCAB - 1 : v);
}
__device__ __forceinline__ u32 smem_to_u32(const void* p) {
    u32 a;
    asm("{ .reg .u64 t; cvta.to.shared.u64 t, %1; cvt.u32.u64 %0, t; }" : "=r"(a) : "l"(p));
    return a;
}
__device__ __forceinline__ void ldsm_x4(u32 addr, u32& r0, u32& r1, u32& r2, u32& r3) {
    asm volatile("ldmatrix.sync.aligned.m8n8.x4.shared.b16 {%0,%1,%2,%3}, [%4];"
                 : "=r"(r0), "=r"(r1), "=r"(r2), "=r"(r3) : "r"(addr));
}
__device__ __forceinline__ void mma_bf16(float* c, u32 a0, u32 a1, u32 a2, u32 a3,
                                         u32 b0, u32 b1) {
    asm volatile(
        "mma.sync.aligned.m16n8k16.row.col.f32.bf16.bf16.f32 "
        "{%0,%1,%2,%3}, {%4,%5,%6,%7}, {%8,%9}, {%0,%1,%2,%3};"
        : "+f"(c[0]), "+f"(c[1]), "+f"(c[2]), "+f"(c[3])
        : "r"(a0), "r"(a1), "r"(a2), "r"(a3), "r"(b0), "r"(b1));
}
__device__ __forceinline__ void cp_async16(u32 dst, const void* src) {
    asm volatile("cp.async.cg.shared.global [%0], [%1], 16;" :: "r"(dst), "l"(src));
}
__device__ __forceinline__ void split_pair(float a, float b, u32& hi, u32& lo) {
    __nv_bfloat16 ha = __float2bfloat16(a);
    __nv_bfloat16 hb = __float2bfloat16(b);
    __nv_bfloat16 la = __float2bfloat16(a - __bfloat162float(ha));
    __nv_bfloat16 lb = __float2bfloat16(b - __bfloat162float(hb));
    hi = ((u32)__bfloat16_as_ushort(hb) << 16) | (u32)__bfloat16_as_ushort(ha);
    lo = ((u32)__bfloat16_as_ushort(lb) << 16) | (u32)__bfloat16_as_ushort(la);
}

__device__ __forceinline__ float warp_sum(float v) {
#pragma unroll
    for (int o = 16; o; o >>= 1) v += __shfl_xor_sync(0xFFFFFFFFu, v, o);
    return v;
}
__device__ __forceinline__ float warp_max(float v) {
#pragma unroll
    for (int o = 16; o; o >>= 1) v = fmaxf(v, __shfl_xor_sync(0xFFFFFFFFu, v, o));
    return v;
}
__device__ __forceinline__ float r16_sum(float v) {
#pragma unroll
    for (int o = 8; o; o >>= 1) v += __shfl_xor_sync(0xFFFFu, v, o, 16);
    return v;
}
__device__ __forceinline__ float r16_max(float v) {
#pragma unroll
    for (int o = 8; o; o >>= 1) v = fmaxf(v, __shfl_xor_sync(0xFFFFu, v, o, 16));
    return v;
}
__device__ __forceinline__ float r16_min(float v) {
#pragma unroll
    for (int o = 8; o; o >>= 1) v = fminf(v, __shfl_xor_sync(0xFFFFu, v, o, 16));
    return v;
}

// ---------------- weight prep ----------------
__global__ void wprep_kernel(const float* __restrict__ Wms,
                             const float* __restrict__ Wmc) {
    int idx = blockIdx.x * blockDim.x + threadIdx.x;
    const int nW = Ff * 5 * KDP;
    if (idx < nW) {
        int f = idx / (5 * KDP);
        int r = idx - f * (5 * KDP);
        int tap = r / KDP;
        int dp = r - tap * KDP;
        int d = 2 * dp;
        float a = (d < Dd) ? Wmc[(size_t)f * Dd * 5 + d * 5 + tap] : 0.f;
        float b = (d + 1 < Dd) ? Wmc[(size_t)f * Dd * 5 + (d + 1) * 5 + tap] : 0.f;
        u32 hi, lo;
        split_pair(a, b, hi, lo);
        g_WbH[idx] = hi;
        g_WbL[idx] = lo;
    } else {
        int i = idx - nW;
        if (i < 2 * Dd * Ff) {
            int f = i % Ff;
            int rest = i / Ff;
            int d = rest % Dd;
            int k = rest / Dd;
            g_Wt_ms[i] = Wms[(size_t)f * Dd * 2 + d * 2 + k];
        }
    }
}

// ---------------- surface conv ----------------
__launch_bounds__(192)
__global__ void conv_ms_kernel(const int* __restrict__ ids,
                               const float* __restrict__ emb,
                               const float* __restrict__ bias) {
    const int m = blockIdx.x;
    const int tid = threadIdx.x;
    __shared__ float Xs[SURF_L * Dd];
    for (int i = tid; i < SURF_L * Dd; i += 192) {
        int l = i / Dd, d = i - l * Dd;
        Xs[i] = emb[(size_t)safe_id(ids, m * SURF_L + l) * Dd + d];
    }
    __syncthreads();
    float4 acc[3];
#pragma unroll
    for (int t = 0; t < 3; t++) acc[t] = make_float4(0.f, 0.f, 0.f, 0.f);
#pragma unroll
    for (int k = 0; k < 2; k++) {
        const float4* __restrict__ wp = (const float4*)(g_Wt_ms + (size_t)k * Dd * Ff) + tid;
        const float* __restrict__ xk = Xs + k * Dd;
        for (int d = 0; d < Dd; d++) {
            float4 w = wp[(size_t)d * (Ff / 4)];
#pragma unroll
            for (int t = 0; t < 3; t++) {
                float xv = xk[t * Dd + d];
                acc[t].x = fmaf(xv, w.x, acc[t].x);
                acc[t].y = fmaf(xv, w.y, acc[t].y);
                acc[t].z = fmaf(xv, w.z, acc[t].z);
                acc[t].w = fmaf(xv, w.w, acc[t].w);
            }
        }
    }
    float4 b4 = ((const float4*)bias)[tid];
    float4 s = make_float4(0.f, 0.f, 0.f, 0.f);
#pragma unroll
    for (int t = 0; t < 3; t++) {
        s.x += fmaxf(acc[t].x + b4.x, 0.f);
        s.y += fmaxf(acc[t].y + b4.y, 0.f);
        s.z += fmaxf(acc[t].z + b4.z, 0.f);
        s.w += fmaxf(acc[t].w + b4.w, 0.f);
    }
    s.x *= (1.f / 3.f); s.y *= (1.f / 3.f); s.z *= (1.f / 3.f); s.w *= (1.f / 3.f);
    ((float4*)(g_ms + (size_t)m * Ff))[tid] = s;
}

// ---------------- context conv: mma.sync + cp.async double-buffered W (R12) ----------------
#define XHALF 31616
#define XMEN (2 * XHALF)
#define WS0 126464
#define WSLAB 40960
#define WS1 (WS0 + WSLAB)
#define SMEM_CONV (WS1 + WSLAB)  // 208384

__global__ void __launch_bounds__(256, 1)
conv_mma2_kernel(const int* __restrict__ ids,
                 const float* __restrict__ emb,
                 const float* __restrict__ bias) {
    extern __shared__ char smem[];
    const int tid = threadIdx.x;
    const int lane = tid & 31;
    const int w = tid >> 5;
    const int mi = w >> 2, nq = w & 3;
    const int mp = blockIdx.x;
    const int f0 = blockIdx.y * 128;

    const u32 sb = smem_to_u32(smem);

    auto stage_issue = [&](int s) {
        int half = s / 10, rem = s - half * 10;
        int tap = rem >> 1, kh = rem & 1;
        const u32* src = half ? g_WbL : g_WbH;
        u32 dst = sb + (u32)((s & 1) ? WS1 : WS0);
        for (int i = tid; i < 128 * 20; i += 256) {
            int row = i / 20, c = i - row * 20;
            const void* g = src + (size_t)(((f0 + row) * 5 + tap) * 38 + kh * 20 + c) * 4;
            cp_async16(dst + (u32)i * 16, g);
        }
    };

    for (int i = tid; i < 2 * 52 * KDP; i += 256) {
        int m2 = i / (52 * KDP);
        int rem = i - m2 * (52 * KDP);
        int row = rem / KDP;
        int dp = rem - row * KDP;
        int d = 2 * dp;
        float a = 0.f, b = 0.f;
        if (row < CTX_L) {
            const float* er = emb + (size_t)safe_id(ids, (mp * 2 + m2) * CTX_L + row) * Dd;
            if (d < Dd) a = er[d];
            if (d + 1 < Dd) b = er[d + 1];
        }
        u32 hi, lo;
        split_pair(a, b, hi, lo);
        ((u32*)(smem + m2 * XMEN))[row * KDP + dp] = hi;
        ((u32*)(smem + m2 * XMEN + XHALF))[row * KDP + dp] = lo;
    }

    const u32 xbase = sb + (u32)(mi * XMEN);
    const int a_r = lane & 15;
    const int a_k = (lane >> 4) << 3;
    const int b_n = ((lane >> 4) << 3) + (lane & 7);
    const int b_k = ((lane >> 3) & 1) << 3;

    float C[3][4][4];
#pragma unroll
    for (int mt = 0; mt < 3; mt++)
#pragma unroll
        for (int nt = 0; nt < 4; nt++)
#pragma unroll
            for (int j = 0; j < 4; j++) C[mt][nt][j] = 0.f;

    stage_issue(0);
    asm volatile("cp.async.commit_group;" ::: "memory");
    __syncthreads();

    for (int s = 0; s < 20; s++) {
        if (s + 1 < 20) stage_issue(s + 1);
        asm volatile("cp.async.commit_group;" ::: "memory");
        asm volatile("cp.async.wait_group 1;" ::: "memory");
        __syncthreads();

        const int half = s / 10, rem = s - half * 10;
        const int tap = rem >> 1, kh = rem & 1;
        const u32 buf = sb + (u32)((s & 1) ? WS1 : WS0);
        const int nks = kh ? 9 : 10;
        const int xk0 = kh ? 160 : 0;
        for (int ks = 0; ks < nks; ks++) {
            const int k0 = ks * 16;
            u32 Bf[4][2];
#pragma unroll
            for (int p = 0; p < 2; p++) {
                u32 addr = buf + (u32)(((nq * 32 + p * 16 + b_n) * 160 + k0 + b_k) * 2);
                ldsm_x4(addr, Bf[2 * p][0], Bf[2 * p][1], Bf[2 * p + 1][0], Bf[2 * p + 1][1]);
            }
#pragma unroll
            for (int mt = 0; mt < 3; mt++) {
                u32 aoff = (u32)(((mt * 16 + tap + a_r) * KD + xk0 + k0 + a_k) * 2);
                u32 A0, A1, A2, A3;
                ldsm_x4(xbase + aoff, A0, A1, A2, A3);
#pragma unroll
                for (int nt = 0; nt < 4; nt++)
                    mma_bf16(C[mt][nt], A0, A1, A2, A3, Bf[nt][0], Bf[nt][1]);
                if (half == 0) {
                    ldsm_x4(xbase + XHALF + aoff, A0, A1, A2, A3);
#pragma unroll
                    for (int nt = 0; nt < 4; nt++)
                        mma_bf16(C[mt][nt], A0, A1, A2, A3, Bf[nt][0], Bf[nt][1]);
                }
            }
        }
        __syncthreads();
    }

    float* stg = (float*)(smem + WS0);
#pragma unroll
    for (int mt = 0; mt < 3; mt++)
#pragma unroll
        for (int nt = 0; nt < 4; nt++) {
            int row = mt * 16 + (lane >> 2);
            int col = nq * 32 + nt * 8 + (lane & 3) * 2;
            float* base = stg + mi * 6144 + row * 128 + col;
            base[0] = C[mt][nt][0];
            base[1] = C[mt][nt][1];
            base[8 * 128] = C[mt][nt][2];
            base[8 * 128 + 1] = C[mt][nt][3];
        }
    __syncthreads();
    {
        int m2 = tid >> 7, f = tid & 127;
        float b = bias[f0 + f];
        float s = 0.f;
        for (int t = 0; t < 46; t++) s += fmaxf(stg[m2 * 6144 + t * 128 + f] + b, 0.f);
        g_mc[(size_t)(mp * 2 + m2) * Ff + f0 + f] = s * (1.0f / 46.0f);
    }
}

// ---------------- cross attention v4: k-split, 2 CTA/SM, no-shift exp ----------------
// Block (n, h, half): E[d=doc 0..99][b_local 0..99] = exp(dot*scale) (scores tiny -> safe)
// dir1 (q=body): fully local per half -> normalized out, partial max -> g_p1
// dir0 (q=doc): partial PV sums g_O0 + partial row sums g_rsp; combined in attmlp
#define A_QS 0
#define A_KS 6000
#define A_E  12000        // stride 101, 100 rows
#define A_CS 22112
#define A_RED 22240
#define SMEM_ATTN ((22240 + 512 + 64) * 4)   // 91264 B

__global__ void __launch_bounds__(256, 2)
attn_kernel(const int* __restrict__ doc_ids,
            const int* __restrict__ body_ids,
            const float* __restrict__ emb) {
    const int n = blockIdx.x, h = blockIdx.y, half = blockIdx.z;
    extern __shared__ float sh[];
    float* qs = sh + A_QS;       // doc [100][60]
    float* ks = sh + A_KS;       // body half [100][60]
    float* E = sh + A_E;         // [100][101]
    float* cs = sh + A_CS;       // col sums [100]
    float* red = sh + A_RED;     // [8][64]

    const int tid = threadIdx.x, wid = tid >> 5, lane = tid & 31;
    const int* bids = body_ids + n * BODY_L + half * 100;
    const int part = (n * NH + h) * 2 + half;

    for (int i = tid; i < 100 * HD; i += 256) {
        int l = i / HD, j = i - l * HD;
        qs[i] = emb[(size_t)safe_id(doc_ids, l) * Dd + h * HD + j];
        ks[i] = emb[(size_t)safe_id(bids, l) * Dd + h * HD + j];
    }
    __syncthreads();

    // ---- E = exp(dot * scale) directly; thread = (d, k-half-of-50)
    const float scale = rsqrtf((float)HD);
    {
        int q = tid >> 1, kh = tid & 1;
        if (q < 100) {
            float4 qv[15];
            const float4* q4 = (const float4*)(qs + q * HD);
#pragma unroll
            for (int j = 0; j < 15; j++) qv[j] = q4[j];
            float* Erow = E + q * 101 + kh * 50;
            for (int i = 0; i < 50; i++) {
                const float4* k4 = (const float4*)(ks + (kh * 50 + i) * HD);
                float a0 = 0.f, a1 = 0.f, a2 = 0.f, a3 = 0.f;
#pragma unroll
                for (int j = 0; j < 15; j++) {
                    float4 kv = k4[j];
                    a0 = fmaf(qv[j].x, kv.x, a0);
                    a1 = fmaf(qv[j].y, kv.y, a1);
                    a2 = fmaf(qv[j].z, kv.z, a2);
                    a3 = fmaf(qv[j].w, kv.w, a3);
                }
                Erow[i] = expf(((a0 + a1) + (a2 + a3)) * scale);
            }
        }
    }
    __syncthreads();

    // ---- partial row sums (dir0) -> global
    for (int q = wid; q < 100; q += 8) {
        float s = 0.f;
        for (int k = lane; k < 100; k += 32) s += E[q * 101 + k];
        s = warp_sum(s);
        if (lane == 0) g_rsp[part * 100 + q] = s;
    }

    // ---- column sums (dir1 denominators; full since all 100 d present)
    for (int c = wid; c < 100; c += 8) {
        float s = 0.f;
        for (int d = lane; d < 100; d += 32) s += E[d * 101 + c];
        s = warp_sum(s);
        if (lane == 0) cs[c] = s;
    }
    __syncthreads();

    // ---- dir0 partial PV: O0p[q][j] = sum_k E[q][k] * body[k][j] (unnormalized)
    if (lane < 30) {
        float2* O0g = (float2*)(g_O0 + (size_t)part * 6000);
        const float2* V = (const float2*)ks;
        for (int g = wid; g < 25; g += 8) {
            int q0 = g * 4;
            float2 a0 = make_float2(0.f, 0.f), a1 = a0, a2 = a0, a3 = a0;
            for (int k = 0; k < 100; k++) {
                float2 v = V[k * 30 + lane];
                float e0 = E[(q0 + 0) * 101 + k];
                float e1 = E[(q0 + 1) * 101 + k];
                float e2 = E[(q0 + 2) * 101 + k];
                float e3 = E[(q0 + 3) * 101 + k];
                a0.x = fmaf(e0, v.x, a0.x); a0.y = fmaf(e0, v.y, a0.y);
                a1.x = fmaf(e1, v.x, a1.x); a1.y = fmaf(e1, v.y, a1.y);
                a2.x = fmaf(e2, v.x, a2.x); a2.y = fmaf(e2, v.y, a2.y);
                a3.x = fmaf(e3, v.x, a3.x); a3.y = fmaf(e3, v.y, a3.y);
            }
            O0g[(q0 + 0) * 30 + lane] = a0;
            O0g[(q0 + 1) * 30 + lane] = a1;
            O0g[(q0 + 2) * 30 + lane] = a2;
            O0g[(q0 + 3) * 30 + lane] = a3;
        }
    }

    // ---- dir1 full (local): out[b][j] = sum_d E[d][b]*doc[d][j] / cs[b], max over b
    {
        float2 mx = make_float2(-1e30f, -1e30f);
        if (lane < 30) {
            const float2* V = (const float2*)qs;
            for (int g = wid; g < 25; g += 8) {
                int b0 = g * 4;
                float2 a0 = make_float2(0.f, 0.f), a1 = a0, a2 = a0, a3 = a0;
                for (int d = 0; d < 100; d++) {
                    float2 v = V[d * 30 + lane];
                    const float* Er = E + d * 101 + b0;
                    float e0 = Er[0], e1 = Er[1], e2 = Er[2], e3 = Er[3];
                    a0.x = fmaf(e0, v.x, a0.x); a0.y = fmaf(e0, v.y, a0.y);
                    a1.x = fmaf(e1, v.x, a1.x); a1.y = fmaf(e1, v.y, a1.y);
                    a2.x = fmaf(e2, v.x, a2.x); a2.y = fmaf(e2, v.y, a2.y);
                    a3.x = fmaf(e3, v.x, a3.x); a3.y = fmaf(e3, v.y, a3.y);
                }
                float i0 = 1.f / cs[b0], i1 = 1.f / cs[b0 + 1];
                float i2 = 1.f / cs[b0 + 2], i3 = 1.f / cs[b0 + 3];
                mx.x = fmaxf(mx.x, fmaxf(fmaxf(a0.x * i0, a1.x * i1), fmaxf(a2.x * i2, a3.x * i3)));
                mx.y = fmaxf(mx.y, fmaxf(fmaxf(a0.y * i0, a1.y * i1), fmaxf(a2.y * i2, a3.y * i3)));
            }
            red[wid * 64 + 2 * lane] = mx.x;
            red[wid * 64 + 2 * lane + 1] = mx.y;
        }
        __syncthreads();
        if (tid < 60) {
            float m = -1e30f;
#pragma unroll
            for (int g = 0; g < 8; g++) m = fmaxf(m, red[g * 64 + tid]);
            g_p1[part * 64 + tid] = m;
        }
    }
}

// ---------------- attention MLP (combines dir0 partials + dir1 maxes) ----------------
__global__ void attmlp_kernel(const float* __restrict__ W1,
                              const float* __restrict__ b1,
                              const float* __restrict__ W2,
                              const float* __restrict__ b2) {
    const int n = blockIdx.x;
    __shared__ float cb[600];
    __shared__ float sinv[500];   // [h][q] 1/(rs0+rs1)
    __shared__ float partial[10];
    const int tid = threadIdx.x;  // 320

    for (int i = tid; i < 500; i += 320) {
        int h = i / 100, q = i - h * 100;
        int b0 = (n * NH + h) * 2;
        sinv[i] = 1.f / (g_rsp[b0 * 100 + q] + g_rsp[(b0 + 1) * 100 + q]);
    }
    __syncthreads();

    for (int i = tid; i < 600; i += 320) {
        float v;
        if (i < 300) {
            int h = i / 60, jj = i - h * 60;
            int b0 = (n * NH + h) * 2;
            const float* P0 = g_O0 + (size_t)b0 * 6000;
            const float* P1 = P0 + 6000;
            const float* iv = sinv + h * 100;
            float m0 = -1e30f, m1 = -1e30f;
            for (int q = 0; q < 100; q += 2) {
                float x0 = (P0[q * 60 + jj] + P1[q * 60 + jj]) * iv[q];
                float x1 = (P0[(q + 1) * 60 + jj] + P1[(q + 1) * 60 + jj]) * iv[q + 1];
                m0 = fmaxf(m0, x0);
                m1 = fmaxf(m1, x1);
            }
            v = fmaxf(m0, m1);
        } else {
            int i2 = i - 300;
            int h = i2 / 60, jj = i2 - h * 60;
            int b0 = (n * NH + h) * 2;
            v = fmaxf(g_p1[b0 * 64 + jj], g_p1[(b0 + 1) * 64 + jj]);
        }
        cb[i] = v;
    }
    __syncthreads();

    float v = 0.f;
    if (tid < 300) {
        float a0 = b1[tid], a1 = 0.f, a2 = 0.f, a3 = 0.f;
        for (int i = 0; i < 600; i += 4) {
            a0 = fmaf(cb[i], W1[i * 300 + tid], a0);
            a1 = fmaf(cb[i + 1], W1[(i + 1) * 300 + tid], a1);
            a2 = fmaf(cb[i + 2], W1[(i + 2) * 300 + tid], a2);
            a3 = fmaf(cb[i + 3], W1[(i + 3) * 300 + tid], a3);
        }
        float a = (a0 + a1) + (a2 + a3);
        a = fmaxf(a, 0.f);
        v = a * W2[tid];
    }
    v = warp_sum(v);
    if ((tid & 31) == 0) partial[tid >> 5] = v;
    __syncthreads();
    if (tid == 0) {
        float s = 0.f;
        for (int w = 0; w < 10; w++) s += partial[w];
        s += b2[0];
        g_attscore[n] = 1.f / (1.f + expf(-s));
    }
}

// ---------------- LocalCtxAttRanker ----------------
__global__ void localctx_kernel(const int* __restrict__ cand_ids,
                                const int* __restrict__ ctx_ids,
                                const float* __restrict__ emb) {
    const int m = blockIdx.x;
    extern __shared__ float sh[];
    float* cs = sh;
    float* xs = cs + Nn * Dd;
    float* tok = xs + CTX_L * Dd;
    float* p = tok + Nn * CTX_L;
    float* ctxv = p + CTX_L;
    const int tid = threadIdx.x;  // 256

    for (int i = tid; i < Nn * Dd; i += 256) {
        int n = i / Dd, d = i - n * Dd;
        cs[i] = emb[(size_t)safe_id(cand_ids, m * Nn + n) * Dd + d];
    }
    for (int i = tid; i < CTX_L * Dd; i += 256) {
        int t = i / Dd, d = i - t * Dd;
        xs[i] = emb[(size_t)safe_id(ctx_ids, m * CTX_L + t) * Dd + d];
    }
    __syncthreads();

    const float4* cs4 = (const float4*)cs;
    const float4* xs4 = (const float4*)xs;
    for (int idx = tid; idx < Nn * CTX_L; idx += 256) {
        int n = idx / CTX_L, t = idx - n * CTX_L;
        float4 a = make_float4(0.f, 0.f, 0.f, 0.f);
#pragma unroll 5
        for (int j = 0; j < 75; j++) {
            float4 cv = cs4[n * 75 + j];
            float4 xv = xs4[t * 75 + j];
            a.x = fmaf(cv.x, xv.x, a.x);
            a.y = fmaf(cv.y, xv.y, a.y);
            a.z = fmaf(cv.z, xv.z, a.z);
            a.w = fmaf(cv.w, xv.w, a.w);
        }
        tok[idx] = (a.x + a.y) + (a.z + a.w);
    }
    __syncthreads();
    if (tid < CTX_L) {
        float mx = -1e30f;
        for (int n = 0; n < Nn; n++) mx = fmaxf(mx, tok[n * CTX_L + tid]);
        p[tid] = mx;
    }
    __syncthreads();
    if (tid < 32) {
        float mx = -1e30f;
        for (int t = tid; t < CTX_L; t += 32) mx = fmaxf(mx, p[t]);
        mx = warp_max(mx);
        float sum = 0.f;
        for (int t = tid; t < CTX_L; t += 32) {
            float e = expf(p[t] - mx);
            p[t] = e;
            sum += e;
        }
        sum = warp_sum(sum);
        float inv = 1.f / sum;
        for (int t = tid; t < CTX_L; t += 32) p[t] *= inv;
    }
    __syncthreads();
    for (int d = tid; d < Dd; d += 256) {
        float s = 0.f;
        for (int t = 0; t < CTX_L; t++) s = fmaf(p[t], xs[t * Dd + d], s);
        ctxv[d] = s;
    }
    __syncthreads();
    const int wid = tid >> 5, lane = tid & 31;
    for (int n = wid; n < Nn; n += 8) {
        float s = 0.f;
        for (int d = lane; d < Dd; d += 32) s = fmaf(cs[n * Dd + d], ctxv[d], s);
        s = warp_sum(s);
        if (lane == 0) g_local[m * Nn + n] = s;
    }
}

// ---------------- prep ----------------
__global__ void prep_kernel(const float* __restrict__ title,
                            const float* __restrict__ md) {
    const int w = threadIdx.x >> 5, lane = threadIdx.x & 31;
    float st2 = 0.f, smt = 0.f, sm2 = 0.f;
    for (int j = lane; j < Ff; j += 32) {
        float t = title[w * Ff + j];
        float mv = md[j];
        st2 = fmaf(t, t, st2);
        smt = fmaf(t, mv, smt);
        sm2 = fmaf(mv, mv, sm2);
    }
    st2 = warp_sum(st2);
    smt = warp_sum(smt);
    sm2 = warp_sum(sm2);
    if (lane == 0) {
        float tnv = sqrtf(st2);
        g_tn[w] = tnv;
        g_cosdt[w] = smt / (fmaxf(sqrtf(sm2), 1e-6f) * fmaxf(tnv, 1e-6f));
    }
}

// ---------------- final ----------------
__global__ void final_kernel(const float* __restrict__ title,
                             const float* __restrict__ prior,
                             const float* __restrict__ hand,
                             const float* __restrict__ w7,
                             const float* __restrict__ b7,
                             float* __restrict__ out) {
    const int m = blockIdx.x;
    const int tid = threadIdx.x;  // 256
    const int wid = tid >> 5, lane = tid & 31;
    __shared__ float nms_s, nmc_s;
    __shared__ float dst[Nn], dct[Nn], sc[Nn];

    if (wid == 0) {
        float s = 0.f;
        for (int j = lane; j < Ff; j += 32) {
            float v = g_ms[m * Ff + j];
            s = fmaf(v, v, s);
        }
        s = warp_sum(s);
        if (lane == 0) nms_s = fmaxf(sqrtf(s), 1e-6f);
    }
    if (wid == 1) {
        float s = 0.f;
        for (int j = lane; j < Ff; j += 32) {
            float v = g_mc[m * Ff + j];
            s = fmaf(v, v, s);
        }
        s = warp_sum(s);
        if (lane == 0) nmc_s = fmaxf(sqrtf(s), 1e-6f);
    }
    for (int item = wid; item < 32; item += 8) {
        int n = item & 15;
        int which = item >> 4;
        const float* a = which ? (g_mc + m * Ff) : (g_ms + m * Ff);
        float s = 0.f;
        for (int j = lane; j < Ff; j += 32) s = fmaf(a[j], title[n * Ff + j], s);
        s = warp_sum(s);
        if (lane == 0) {
            if (which) dct[n] = s;
            else dst[n] = s;
        }
    }
    __syncthreads();

    if (tid < Nn) {
        int n = tid;
        float tc = fmaxf(g_tn[n], 1e-6f);
        float cst = dst[n] / (nms_s * tc);
        float cct = dct[n] / (nmc_s * tc);
        float s = b7[0];
        s = fmaf(w7[0], hand[n], s);
        s = fmaf(w7[1], prior[n], s);
        s = fmaf(w7[2], g_local[m * Nn + n], s);
        s = fmaf(w7[3], g_attscore[n], s);
        s = fmaf(w7[4], cst, s);
        s = fmaf(w7[5], g_cosdt[n], s);
        s = fmaf(w7[6], cct, s);
        sc[n] = s;
    }
    __syncthreads();
    if (tid < Nn) {
        float x = sc[tid];
        float mu = r16_sum(x) * (1.f / 16.f);
        float dv = x - mu;
        float var = r16_sum(dv * dv) * (1.f / 15.f);
        float z = dv / sqrtf(var);
        out[m * Nn + tid] = z;
        float zmax = r16_max(z);
        float zmin = r16_min(z);
        float e = expf(z - zmax);
        float es = r16_sum(e);
        out[Mm * Nn + m * Nn + tid] = e / es;
        float u = (z + 1.f - zmin) / (zmax - zmin);
        float us = r16_sum(u);
        out[2 * Mm * Nn + m * Nn + tid] = u / us;
    }
}

// ---------------- launch ----------------
extern "C" void kernel_launch(void* const* d_in, const int* in_sizes, int n_in,
                              void* d_out, int out_size) {
    int e = -1;
    for (int i = 0; i < n_in; i++) {
        if (in_sizes[i] == VOCAB * Dd) { e = i; break; }
    }
    if (e < 0) e = 14;

    const int* mention_vec  = (const int*)d_in[e - 11];
    const int* context_vec  = (const int*)d_in[e - 10];
    const int* doc_vec      = (const int*)d_in[e - 9];
    const float* title      = (const float*)d_in[e - 8];
    const int* body_vec     = (const int*)d_in[e - 7];
    const float* prior      = (const float*)d_in[e - 5];
    const int* men2cands    = (const int*)d_in[e - 4];
    const int* contexts_ids = (const int*)d_in[e - 3];
    const float* hand       = (const float*)d_in[e - 2];
    const float* bert       = (const float*)d_in[e - 1];
    const float* emb        = (const float*)d_in[e];
    const float* Wms        = (const float*)d_in[e + 1];
    const float* bms        = (const float*)d_in[e + 2];
    const float* Wmc        = (const float*)d_in[e + 3];
    const float* bmc        = (const float*)d_in[e + 4];
    const float* w7         = (const float*)d_in[e + 5];
    const float* b7         = (const float*)d_in[e + 6];
    const float* W1         = (const float*)d_in[e + 7];
    const float* b1         = (const float*)d_in[e + 8];
    const float* W2         = (const float*)d_in[e + 9];
    const float* b2         = (const float*)d_in[e + 10];
    float* out = (float*)d_out;

    static bool s_init = false;
    static cudaStream_t s0, s1, s2;
    static cudaEvent_t evF, ev0, ev1, ev2;
    if (!s_init) {
        cudaStreamCreateWithFlags(&s0, cudaStreamNonBlocking);
        cudaStreamCreateWithFlags(&s1, cudaStreamNonBlocking);
        cudaStreamCreateWithFlags(&s2, cudaStreamNonBlocking);
        cudaEventCreateWithFlags(&evF, cudaEventDisableTiming);
        cudaEventCreateWithFlags(&ev0, cudaEventDisableTiming);
        cudaEventCreateWithFlags(&ev1, cudaEventDisableTiming);
        cudaEventCreateWithFlags(&ev2, cudaEventDisableTiming);
        s_init = true;
    }

    cudaFuncSetAttribute(attn_kernel, cudaFuncAttributeMaxDynamicSharedMemorySize, SMEM_ATTN);
    cudaFuncSetAttribute(localctx_kernel, cudaFuncAttributeMaxDynamicSharedMemorySize, 84000);
    cudaFuncSetAttribute(conv_mma2_kernel, cudaFuncAttributeMaxDynamicSharedMemorySize, SMEM_CONV);

    cudaEventRecord(evF, 0);
    cudaStreamWaitEvent(s0, evF, 0);
    cudaStreamWaitEvent(s1, evF, 0);
    cudaStreamWaitEvent(s2, evF, 0);

    // s0: weight prep -> convs
    wprep_kernel<<<(Ff * 5 * KDP + 2 * Dd * Ff + 255) / 256, 256, 0, s0>>>(Wms, Wmc);
    conv_ms_kernel<<<Mm, 192, 0, s0>>>(mention_vec, emb, bms);
    conv_mma2_kernel<<<dim3(Mm / 2, Ff / 128), 256, SMEM_CONV, s0>>>(context_vec, emb, bmc);
    cudaEventRecord(ev0, s0);

    // s1: cross attention (k-split) + MLP score (with combine)
    attn_kernel<<<dim3(Nn, NH, 2), 256, SMEM_ATTN, s1>>>(doc_vec, body_vec, emb);
    attmlp_kernel<<<Nn, 320, 0, s1>>>(W1, b1, W2, b2);
    cudaEventRecord(ev1, s1);

    // s2: local context ranker + title prep
    localctx_kernel<<<Mm, 256, 84000, s2>>>(men2cands, contexts_ids, emb);
    prep_kernel<<<1, 512, 0, s2>>>(title, bert);
    cudaEventRecord(ev2, s2);

    cudaStreamWaitEvent(0, ev0, 0);
    cudaStreamWaitEvent(0, ev1, 0);
    cudaStreamWaitEvent(0, ev2, 0);

    final_kernel<<<Mm, 256>>>(title, prior, hand, w7, b7, out);
}